// round 10
// baseline (speedup 1.0000x reference)
#include <cuda_runtime.h>
#include <cuda_fp16.h>
#include <math.h>
#include <stdint.h>

#define TSEQ 2048
#define HID  4096
#define NH   32
#define NKV  8
#define DH   128
#define GRP  (NH / NKV)

// ---------------------------------------------------------------------------
// Scratch (allocation-free rule: __device__ globals)
// ---------------------------------------------------------------------------
__device__ float g_q[(size_t)TSEQ * NH * DH];            // fp32 Q (pre-rope)
__device__ float2 g_tab[(size_t)TSEQ * 64];              // rope (cos,sin)
__device__ __half g_hsh[(size_t)TSEQ * HID], g_hsl[(size_t)TSEQ * HID];
__device__ __half g_wq[(size_t)HID * NH * DH];
__device__ __half g_wk[(size_t)HID * NKV * DH];
__device__ __half g_wv[(size_t)HID * NKV * DH];
__device__ __half g_wo[(size_t)NH * DH * HID];
__device__ __half g_qh[(size_t)TSEQ * NH * DH], g_ql[(size_t)TSEQ * NH * DH];
__device__ __half g_ktr[(size_t)NKV * DH * TSEQ];        // K transposed [h][d][t]
__device__ __half g_v[(size_t)TSEQ * NKV * DH];
__device__ __half g_ah[(size_t)TSEQ * NH * DH], g_al[(size_t)TSEQ * NH * DH];

// ---------------------------------------------------------------------------
// helpers
// ---------------------------------------------------------------------------
__device__ __forceinline__ uint32_t smem_u32(const void* p) {
    uint32_t a;
    asm("{ .reg .u64 t; cvta.to.shared.u64 t, %1; cvt.u32.u64 %0, t; }"
        : "=r"(a) : "l"(p));
    return a;
}
__device__ __forceinline__ uint32_t pack_f16x2(float x, float y) {
    __half2 h = __floats2half2_rn(x, y);
    return *(uint32_t*)&h;
}
__device__ __forceinline__ void split_pack_f16(float x, float y,
                                               uint32_t& hi, uint32_t& lo) {
    __half2 h = __floats2half2_rn(x, y);
    float2 b = __half22float2(h);
    __half2 l = __floats2half2_rn(x - b.x, y - b.y);
    hi = *(uint32_t*)&h;
    lo = *(uint32_t*)&l;
}
__device__ __forceinline__ void ldsm4(uint32_t (&r)[4], uint32_t a) {
    asm volatile("ldmatrix.sync.aligned.m8n8.x4.shared.b16 {%0,%1,%2,%3}, [%4];"
        : "=r"(r[0]), "=r"(r[1]), "=r"(r[2]), "=r"(r[3]) : "r"(a));
}
__device__ __forceinline__ void ldsm4t(uint32_t (&r)[4], uint32_t a) {
    asm volatile("ldmatrix.sync.aligned.m8n8.x4.trans.shared.b16 {%0,%1,%2,%3}, [%4];"
        : "=r"(r[0]), "=r"(r[1]), "=r"(r[2]), "=r"(r[3]) : "r"(a));
}
__device__ __forceinline__ void mma_f16(float (&c)[4], const uint32_t (&a)[4],
                                        uint32_t b0, uint32_t b1) {
    asm volatile("mma.sync.aligned.m16n8k16.row.col.f32.f16.f16.f32 "
        "{%0,%1,%2,%3}, {%4,%5,%6,%7}, {%8,%9}, {%0,%1,%2,%3};"
        : "+f"(c[0]), "+f"(c[1]), "+f"(c[2]), "+f"(c[3])
        : "r"(a[0]), "r"(a[1]), "r"(a[2]), "r"(a[3]), "r"(b0), "r"(b1));
}
__device__ __forceinline__ void cp16(uint32_t dst, const void* src) {
    asm volatile("cp.async.cg.shared.global [%0], [%1], 16;" :: "r"(dst), "l"(src));
}
#define CP_COMMIT() asm volatile("cp.async.commit_group;" ::: "memory")
#define CP_WAIT(n)  asm volatile("cp.async.wait_group %0;" :: "n"(n) : "memory")

// ---------------------------------------------------------------------------
// Fused prep: hs hi/lo split + all 4 weight converts + rope table.
// ---------------------------------------------------------------------------
#define HS_T  (TSEQ * HID / 8)
#define WQ_T  (HID * NH * DH / 8)
#define WK_T  (HID * NKV * DH / 8)
#define WV_T  (HID * NKV * DH / 8)
#define WO_T  (NH * DH * HID / 8)
#define TAB_T (TSEQ * 64)
#define PREP_TOT (HS_T + WQ_T + WK_T + WV_T + WO_T + TAB_T)

__global__ void prep_kernel(const int* __restrict__ positions,
                            const float4* __restrict__ hs,
                            const float4* __restrict__ wq,
                            const float4* __restrict__ wk,
                            const float4* __restrict__ wv,
                            const float4* __restrict__ wo)
{
    int i = blockIdx.x * blockDim.x + threadIdx.x;
    if (i >= PREP_TOT) return;
    int j = i;
    if (j < HS_T) {
        float4 v0 = hs[j * 2];
        float4 v1 = hs[j * 2 + 1];
        uint32_t h0, l0, h1, l1, h2, l2, h3, l3;
        split_pack_f16(v0.x, v0.y, h0, l0);
        split_pack_f16(v0.z, v0.w, h1, l1);
        split_pack_f16(v1.x, v1.y, h2, l2);
        split_pack_f16(v1.z, v1.w, h3, l3);
        ((uint4*)g_hsh)[j] = make_uint4(h0, h1, h2, h3);
        ((uint4*)g_hsl)[j] = make_uint4(l0, l1, l2, l3);
        return;
    }
    j -= HS_T;
    const float4* src;
    uint4* dst;
    if (j < WQ_T)                 { src = wq; dst = (uint4*)g_wq; }
    else if ((j -= WQ_T) < WK_T)  { src = wk; dst = (uint4*)g_wk; }
    else if ((j -= WK_T) < WV_T)  { src = wv; dst = (uint4*)g_wv; }
    else if ((j -= WV_T) < WO_T)  { src = wo; dst = (uint4*)g_wo; }
    else {
        j -= WO_T;                 // rope table entry
        int d = j & 63, t = j >> 6;
        float pos = (float)positions[t];
        float inv_freq = powf(1.0e6f, -(float)d * (1.0f / 64.0f));
        float s, c;
        sincosf(pos * inv_freq, &s, &c);
        g_tab[j] = make_float2(c, s);
        return;
    }
    float4 v0 = src[j * 2];
    float4 v1 = src[j * 2 + 1];
    dst[j] = make_uint4(pack_f16x2(v0.x, v0.y), pack_f16x2(v0.z, v0.w),
                        pack_f16x2(v1.x, v1.y), pack_f16x2(v1.z, v1.w));
}

// ---------------------------------------------------------------------------
// Core GEMM tile: C[bm:+128, bn:+128] = A@B (+bias). A fp16 hi/lo split,
// B plain fp16. 3-stage cp.async pipeline, K-chunk 32, ONE sync per chunk.
// 256 threads (4Mx2N warps), 2 CTAs/SM.
// ---------------------------------------------------------------------------
#define TG_AT 10240u            // A half-tile [128][80B]  (64B data + 16 pad)
#define TG_BT 8704u             // B tile [32][272B]       (256B data + 16 pad)
#define TG_BUF (2u * TG_AT + TG_BT)         // 29184
#define TG_STAGES 3
#define TG_SMEM (TG_STAGES * TG_BUF)        // 87552

__device__ __forceinline__ void gemm_tile(
    const __half* __restrict__ Ah, const __half* __restrict__ Al,
    const __half* __restrict__ B,
    const float* __restrict__ bias, float* __restrict__ C,
    __half* __restrict__ Ch,
    int N, int K, int bm, int bn, char* sm)
{
    const uint32_t sb = smem_u32(sm);
    const int tid  = threadIdx.x;
    const int wid  = tid >> 5;
    const int lane = tid & 31;
    const int wm = (wid >> 1) << 5;
    const int wn = (wid & 1) << 6;

    auto issue = [&](int k0, int buf) {
        const uint32_t base = sb + (uint32_t)buf * TG_BUF;
        #pragma unroll
        for (int i = 0; i < 2; i++) {
            int idx = tid + i * 256;          // 0..511
            int ar = idx >> 2, ac = idx & 3;  // A: 128 rows x 4 16B-chunks
            const size_t aoff = (size_t)(bm + ar) * K + k0 + ac * 8;
            cp16(base + (uint32_t)(ar * 80 + ac * 16), Ah + aoff);
            cp16(base + TG_AT + (uint32_t)(ar * 80 + ac * 16), Al + aoff);
            int br = idx >> 4, bc = idx & 15; // B: 32 rows x 16 16B-chunks
            const size_t boff = (size_t)(k0 + br) * N + bn + bc * 8;
            cp16(base + 2u * TG_AT + (uint32_t)(br * 272 + bc * 16), B + boff);
        }
    };

    float acc[2][8][4];
    #pragma unroll
    for (int mi = 0; mi < 2; mi++)
        #pragma unroll
        for (int j = 0; j < 8; j++)
            #pragma unroll
            for (int q = 0; q < 4; q++) acc[mi][j][q] = 0.f;

    const int NC = K >> 5;    // chunks of 32
    issue(0, 0);  CP_COMMIT();
    issue(32, 1); CP_COMMIT();

    for (int c = 0; c < NC; c++) {
        // wait for chunk c to land (pending may include c+1)
        if (c + 1 < NC) { CP_WAIT(1); } else { CP_WAIT(0); }
        __syncthreads();                       // publish chunk c to all warps
        if (c + 2 < NC) { issue((c + 2) << 5, (c + 2) % TG_STAGES); CP_COMMIT(); }

        const uint32_t base = sb + (uint32_t)(c % TG_STAGES) * TG_BUF;
        #pragma unroll
        for (int ks = 0; ks < 2; ks++) {
            uint32_t afh[2][4], afl[2][4];
            #pragma unroll
            for (int mi = 0; mi < 2; mi++) {
                uint32_t ro = base + (uint32_t)((wm + mi * 16 + (lane & 15)) * 80
                                                + ks * 32 + (lane >> 4) * 16);
                ldsm4(afh[mi], ro);
                ldsm4(afl[mi], ro + TG_AT);
            }
            uint32_t bf[4][4];
            const uint32_t kro = base + 2u * TG_AT
                + (uint32_t)((ks * 16 + (lane & 15)) * 272 + (lane >> 4) * 16);
            #pragma unroll
            for (int nb = 0; nb < 4; nb++)
                ldsm4t(bf[nb], kro + (uint32_t)((wn + nb * 16) * 2));
            #pragma unroll
            for (int mi = 0; mi < 2; mi++)
                #pragma unroll
                for (int nb = 0; nb < 4; nb++)
                    #pragma unroll
                    for (int hh = 0; hh < 2; hh++) {
                        float (&cc)[4] = acc[mi][nb * 2 + hh];
                        mma_f16(cc, afh[mi], bf[nb][2 * hh], bf[nb][2 * hh + 1]);
                        mma_f16(cc, afl[mi], bf[nb][2 * hh], bf[nb][2 * hh + 1]);
                    }
        }
    }

    // epilogue
    const int r0 = lane >> 2;
    const int c0 = (lane & 3) << 1;
    #pragma unroll
    for (int mi = 0; mi < 2; mi++) {
        #pragma unroll
        for (int j = 0; j < 8; j++) {
            const int col = bn + wn + j * 8 + c0;
            float bias0 = 0.f, bias1 = 0.f;
            if (bias != nullptr) { bias0 = bias[col]; bias1 = bias[col + 1]; }
            const int row_a = bm + wm + mi * 16 + r0;
            const int row_b = row_a + 8;
            float va0 = acc[mi][j][0] + bias0, va1 = acc[mi][j][1] + bias1;
            float vb0 = acc[mi][j][2] + bias0, vb1 = acc[mi][j][3] + bias1;
            float* Ca = C + (size_t)row_a * N + col;
            float* Cb = C + (size_t)row_b * N + col;
            Ca[0] = va0; Ca[1] = va1;
            Cb[0] = vb0; Cb[1] = vb1;
            if (Ch != nullptr) {
                *(uint32_t*)(Ch + (size_t)row_a * N + col) = pack_f16x2(va0, va1);
                *(uint32_t*)(Ch + (size_t)row_b * N + col) = pack_f16x2(vb0, vb1);
            }
        }
    }
}

// Fused QKV projection: grid (48, 16). bx<32 -> Q, [32,40) -> K, [40,48) -> V.
__global__ __launch_bounds__(256, 2) void tgemm_qkv(
    const float* __restrict__ bq, const float* __restrict__ bk,
    const float* __restrict__ bv,
    float* __restrict__ qbuf, float* __restrict__ kout, float* __restrict__ vout)
{
    extern __shared__ char sm[];
    const int bx = blockIdx.x;
    const int bm = blockIdx.y << 7;
    if (bx < 32) {
        gemm_tile(g_hsh, g_hsl, g_wq, bq, qbuf, nullptr,
                  NH * DH, HID, bm, bx << 7, sm);
    } else if (bx < 40) {
        gemm_tile(g_hsh, g_hsl, g_wk, bk, kout, nullptr,
                  NKV * DH, HID, bm, (bx - 32) << 7, sm);
    } else {
        gemm_tile(g_hsh, g_hsl, g_wv, bv, vout, g_v,
                  NKV * DH, HID, bm, (bx - 40) << 7, sm);
    }
}

// O projection: grid (32, 16).
__global__ __launch_bounds__(256, 2) void tgemm_o(float* __restrict__ out)
{
    extern __shared__ char sm[];
    gemm_tile(g_ah, g_al, g_wo, nullptr, out, nullptr,
              HID, NH * DH, blockIdx.y << 7, blockIdx.x << 7, sm);
}

// ---------------------------------------------------------------------------
// Fused rope: first TSEQ*NH*64 indices -> Q path, rest -> K path.
// ---------------------------------------------------------------------------
#define RQ_T (TSEQ * NH * 64)
#define RK_T (TSEQ * NKV * 64)

__global__ void rope_kernel(const float* __restrict__ q, float* __restrict__ k)
{
    int i = blockIdx.x * blockDim.x + threadIdx.x;
    if (i >= RQ_T + RK_T) return;
    if (i < RQ_T) {
        int d = i & 63;
        int rest = i >> 6;
        int hh = rest % NH;
        int t  = rest / NH;
        const float scale = 0.08838834764831843f;
        float2 cs = g_tab[t * 64 + d];
        size_t base = (size_t)t * (NH * DH) + (size_t)hh * DH;
        float x1 = q[base + d];
        float x2 = q[base + d + 64];
        float y1 = (x1 * cs.x - x2 * cs.y) * scale;
        float y2 = (x2 * cs.x + x1 * cs.y) * scale;
        __half h1 = __float2half_rn(y1);
        __half h2 = __float2half_rn(y2);
        g_qh[base + d]      = h1;
        g_ql[base + d]      = __float2half_rn(y1 - __half2float(h1));
        g_qh[base + d + 64] = h2;
        g_ql[base + d + 64] = __float2half_rn(y2 - __half2float(h2));
    } else {
        int j = i - RQ_T;
        int d = j & 63;
        int rest = j >> 6;
        int hh = rest % NKV;
        int t  = rest / NKV;
        float2 cs = g_tab[t * 64 + d];
        size_t base = (size_t)t * (NKV * DH) + (size_t)hh * DH;
        float x1 = k[base + d];
        float x2 = k[base + d + 64];
        float y1 = x1 * cs.x - x2 * cs.y;
        float y2 = x2 * cs.x + x1 * cs.y;
        k[base + d]      = y1;
        k[base + d + 64] = y2;
        g_ktr[((size_t)hh * DH + d) * TSEQ + t]      = __float2half_rn(y1);
        g_ktr[((size_t)hh * DH + d + 64) * TSEQ + t] = __float2half_rn(y2);
    }
}

// ---------------------------------------------------------------------------
// MMA flash attention: 128 q-rows/CTA, 256 threads. Q fp16 hi/lo (pre-scaled),
// K/V plain fp16 (K pre-transposed), P split x2. cp.async 2-stage KV.
// Grid (NH, T/128); m0 reversed for wave balance. (unchanged from R9)
// ---------------------------------------------------------------------------
#define A2_Q  34816u    // [128][272B]
#define A2_KT 18432u    // [128][144B]
#define A2_V  17408u    // [64][272B]
#define O_QH 0u
#define O_QL A2_Q
#define O_KV0 (2u * A2_Q)
#define KV_BUF (A2_KT + A2_V)
#define A2_SMEM (2u * A2_Q + 2u * KV_BUF)   // 141312

__global__ __launch_bounds__(256, 1) void attn_mma(
    __half* __restrict__ oh, __half* __restrict__ ol)
{
    extern __shared__ char sm[];
    const uint32_t sb = smem_u32(sm);
    const int h  = blockIdx.x;
    const int m0 = (int)(gridDim.y - 1 - blockIdx.y) << 7;
    const int kvh = h / GRP;
    const int tid = threadIdx.x;
    const int wid = tid >> 5;
    const int lane = tid & 31;
    const int wm = wid << 4;
    const int gID = lane >> 2;
    const int tig = lane & 3;

    const __half* ktr_h = g_ktr + (size_t)kvh * DH * TSEQ;

    auto issue_kv = [&](int n0, int b) {
        const uint32_t kb = sb + O_KV0 + (uint32_t)b * KV_BUF;
        #pragma unroll
        for (int i = 0; i < 4; i++) {
            int idx = tid + i * 256;
            int dr = idx >> 3, dc = idx & 7;
            cp16(kb + (uint32_t)(dr * 144 + dc * 16),
                 ktr_h + (size_t)dr * TSEQ + n0 + dc * 8);
            int vr = idx >> 4, vc = idx & 15;
            cp16(kb + A2_KT + (uint32_t)(vr * 272 + vc * 16),
                 g_v + (size_t)(n0 + vr) * (NKV * DH) + (size_t)kvh * DH + vc * 8);
        }
    };

    // load Q tile (128 x 128) hi/lo
    #pragma unroll
    for (int i = 0; i < 8; i++) {
        int idx = tid + i * 256;
        int r = idx >> 4, ch = idx & 15;
        const size_t go = (size_t)(m0 + r) * (NH * DH) + (size_t)h * DH + ch * 8;
        *(uint4*)(sm + O_QH + r * 272 + ch * 16) = *(const uint4*)(g_qh + go);
        *(uint4*)(sm + O_QL + r * 272 + ch * 16) = *(const uint4*)(g_ql + go);
    }

    float oacc[16][4];
    #pragma unroll
    for (int j = 0; j < 16; j++)
        #pragma unroll
        for (int q = 0; q < 4; q++) oacc[j][q] = 0.f;
    float m_run0 = -1e30f, m_run1 = -1e30f, l_run0 = 0.f, l_run1 = 0.f;

    const int row0 = m0 + wm + gID;
    const int row1 = row0 + 8;
    const int warp_max_row = m0 + wm + 15;

    const int nblocks = (m0 >> 6) + 2;
    issue_kv(0, 0); CP_COMMIT();

    for (int blk = 0; blk < nblocks; blk++) {
        const int n0 = blk << 6;
        const bool more = (blk + 1 < nblocks);
        if (more) { issue_kv((blk + 1) << 6, (blk + 1) & 1); CP_COMMIT(); CP_WAIT(1); }
        else      { CP_WAIT(0); }
        __syncthreads();

        if (n0 <= warp_max_row) {
            const uint32_t kb = sb + O_KV0 + (uint32_t)(blk & 1) * KV_BUF;

            // ---- S = Q K^T (2 products) ----
            float sacc[8][4];
            #pragma unroll
            for (int j = 0; j < 8; j++)
                #pragma unroll
                for (int q = 0; q < 4; q++) sacc[j][q] = 0.f;

            #pragma unroll
            for (int ks = 0; ks < 8; ks++) {
                uint32_t aH[4], aL[4];
                uint32_t ro = sb + O_QH + (uint32_t)((wm + (lane & 15)) * 272
                                                     + ks * 32 + (lane >> 4) * 16);
                ldsm4(aH, ro);
                ldsm4(aL, ro + A2_Q);
                const uint32_t kro = kb
                    + (uint32_t)((ks * 16 + (lane & 15)) * 144 + (lane >> 4) * 16);
                #pragma unroll
                for (int nb = 0; nb < 4; nb++) {
                    uint32_t bk4[4];
                    ldsm4t(bk4, kro + (uint32_t)(nb * 32));
                    #pragma unroll
                    for (int hh = 0; hh < 2; hh++) {
                        float (&cc)[4] = sacc[nb * 2 + hh];
                        mma_f16(cc, aH, bk4[2 * hh], bk4[2 * hh + 1]);
                        mma_f16(cc, aL, bk4[2 * hh], bk4[2 * hh + 1]);
                    }
                }
            }

            // ---- online softmax ----
            float mx0 = -1e30f, mx1 = -1e30f;
            #pragma unroll
            for (int nb = 0; nb < 8; nb++) {
                #pragma unroll
                for (int j = 0; j < 2; j++) {
                    const int col = n0 + nb * 8 + tig * 2 + j;
                    float s0 = sacc[nb][j];
                    float s1 = sacc[nb][2 + j];
                    if (col > row0) s0 = -1e30f;
                    if (col > row1) s1 = -1e30f;
                    sacc[nb][j] = s0;
                    sacc[nb][2 + j] = s1;
                    mx0 = fmaxf(mx0, s0);
                    mx1 = fmaxf(mx1, s1);
                }
            }
            #pragma unroll
            for (int off = 1; off <= 2; off <<= 1) {
                mx0 = fmaxf(mx0, __shfl_xor_sync(0xffffffffu, mx0, off));
                mx1 = fmaxf(mx1, __shfl_xor_sync(0xffffffffu, mx1, off));
            }
            float mn0 = fmaxf(m_run0, mx0);
            float mn1 = fmaxf(m_run1, mx1);
            float cf0 = __expf(m_run0 - mn0);
            float cf1 = __expf(m_run1 - mn1);
            m_run0 = mn0; m_run1 = mn1;
            float su0 = 0.f, su1 = 0.f;
            #pragma unroll
            for (int nb = 0; nb < 8; nb++) {
                #pragma unroll
                for (int j = 0; j < 2; j++) {
                    float p0 = __expf(sacc[nb][j] - mn0);
                    float p1 = __expf(sacc[nb][2 + j] - mn1);
                    sacc[nb][j] = p0;
                    sacc[nb][2 + j] = p1;
                    su0 += p0;
                    su1 += p1;
                }
            }
            #pragma unroll
            for (int off = 1; off <= 2; off <<= 1) {
                su0 += __shfl_xor_sync(0xffffffffu, su0, off);
                su1 += __shfl_xor_sync(0xffffffffu, su1, off);
            }
            l_run0 = l_run0 * cf0 + su0;
            l_run1 = l_run1 * cf1 + su1;
            #pragma unroll
            for (int j = 0; j < 16; j++) {
                oacc[j][0] *= cf0;
                oacc[j][1] *= cf0;
                oacc[j][2] *= cf1;
                oacc[j][3] *= cf1;
            }

            // ---- O += P V (2 products; P split register-direct) ----
            #pragma unroll
            for (int ks = 0; ks < 4; ks++) {
                uint32_t ph[4], pl[4];
                split_pack_f16(sacc[2 * ks][0],     sacc[2 * ks][1],     ph[0], pl[0]);
                split_pack_f16(sacc[2 * ks][2],     sacc[2 * ks][3],     ph[1], pl[1]);
                split_pack_f16(sacc[2 * ks + 1][0], sacc[2 * ks + 1][1], ph[2], pl[2]);
                split_pack_f16(sacc[2 * ks + 1][2], sacc[2 * ks + 1][3], ph[3], pl[3]);
                const uint32_t vro = kb + A2_KT
                    + (uint32_t)((ks * 16 + (lane & 15)) * 272 + (lane >> 4) * 16);
                #pragma unroll
                for (int nbv = 0; nbv < 8; nbv++) {
                    uint32_t vb4[4];
                    ldsm4t(vb4, vro + (uint32_t)(nbv * 32));
                    #pragma unroll
                    for (int hh = 0; hh < 2; hh++) {
                        float (&cc)[4] = oacc[nbv * 2 + hh];
                        mma_f16(cc, ph, vb4[2 * hh], vb4[2 * hh + 1]);
                        mma_f16(cc, pl, vb4[2 * hh], vb4[2 * hh + 1]);
                    }
                }
            }
        }
        __syncthreads();
    }

    // epilogue: write fp16 hi/lo split of normalized output
    const float inv0 = 1.0f / l_run0;
    const float inv1 = 1.0f / l_run1;
    #pragma unroll
    for (int onb = 0; onb < 16; onb++) {
        const int col = h * DH + onb * 8 + tig * 2;
        const size_t i0 = (size_t)row0 * (NH * DH) + col;
        const size_t i1 = (size_t)row1 * (NH * DH) + col;
        uint32_t hh_, ll_;
        split_pack_f16(oacc[onb][0] * inv0, oacc[onb][1] * inv0, hh_, ll_);
        *(uint32_t*)(oh + i0) = hh_;
        *(uint32_t*)(ol + i0) = ll_;
        split_pack_f16(oacc[onb][2] * inv1, oacc[onb][3] * inv1, hh_, ll_);
        *(uint32_t*)(oh + i1) = hh_;
        *(uint32_t*)(ol + i1) = ll_;
    }
}

// ---------------------------------------------------------------------------
extern "C" void kernel_launch(void* const* d_in, const int* in_sizes, int n_in,
                              void* d_out, int out_size)
{
    const int*   positions = (const int*)d_in[0];
    const float* hs = (const float*)d_in[1];
    const float* Wq = (const float*)d_in[2];
    const float* bq = (const float*)d_in[3];
    const float* Wk = (const float*)d_in[4];
    const float* bk = (const float*)d_in[5];
    const float* Wv = (const float*)d_in[6];
    const float* bv = (const float*)d_in[7];
    const float* Wo = (const float*)d_in[8];

    float* out  = (float*)d_out;
    float* kout = out + (size_t)TSEQ * HID;
    float* vout = kout + (size_t)TSEQ * NKV * DH;

    float *qbuf;
    __half *aah, *aal;
    cudaGetSymbolAddress((void**)&qbuf, g_q);
    cudaGetSymbolAddress((void**)&aah, g_ah);
    cudaGetSymbolAddress((void**)&aal, g_al);

    cudaFuncSetAttribute(tgemm_qkv, cudaFuncAttributeMaxDynamicSharedMemorySize, (int)TG_SMEM);
    cudaFuncSetAttribute(tgemm_o, cudaFuncAttributeMaxDynamicSharedMemorySize, (int)TG_SMEM);
    cudaFuncSetAttribute(attn_mma, cudaFuncAttributeMaxDynamicSharedMemorySize, (int)A2_SMEM);

    // 1. fused prep (hs split, weight converts, rope table)
    prep_kernel<<<(PREP_TOT + 255) / 256, 256>>>(
        positions, (const float4*)hs, (const float4*)Wq, (const float4*)Wk,
        (const float4*)Wv, (const float4*)Wo);

    // 2. fused QKV projection
    tgemm_qkv<<<dim3(48, 16), 256, TG_SMEM>>>(bq, bk, bv, qbuf, kout, vout);

    // 3. fused rope
    rope_kernel<<<(RQ_T + RK_T + 255) / 256, 256>>>(qbuf, kout);

    // 4. attention
    attn_mma<<<dim3(NH, TSEQ / 128), 256, A2_SMEM>>>(aah, aal);

    // 5. O projection
    tgemm_o<<<dim3(32, 16), 256, TG_SMEM>>>(out);
}

// round 11
// speedup vs baseline: 1.0610x; 1.0610x over previous
#include <cuda_runtime.h>
#include <cuda_fp16.h>
#include <math.h>
#include <stdint.h>

#define TSEQ 2048
#define HID  4096
#define NH   32
#define NKV  8
#define DH   128
#define GRP  (NH / NKV)

// ---------------------------------------------------------------------------
// Scratch (allocation-free rule: __device__ globals)
// ---------------------------------------------------------------------------
__device__ float g_q[(size_t)TSEQ * NH * DH];            // fp32 Q (pre-rope)
__device__ float2 g_tab[(size_t)TSEQ * 64];              // rope (cos,sin)
__device__ __half g_hsh[(size_t)TSEQ * HID], g_hsl[(size_t)TSEQ * HID];
__device__ __half g_wq[(size_t)HID * NH * DH];
__device__ __half g_wk[(size_t)HID * NKV * DH];
__device__ __half g_wv[(size_t)HID * NKV * DH];
__device__ __half g_wo[(size_t)NH * DH * HID];
__device__ __half g_qh[(size_t)TSEQ * NH * DH], g_ql[(size_t)TSEQ * NH * DH];
__device__ __half g_ktr[(size_t)NKV * DH * TSEQ];        // K transposed [h][d][t]
__device__ __half g_v[(size_t)TSEQ * NKV * DH];
__device__ __half g_ah[(size_t)TSEQ * NH * DH], g_al[(size_t)TSEQ * NH * DH];

// ---------------------------------------------------------------------------
// helpers
// ---------------------------------------------------------------------------
__device__ __forceinline__ uint32_t smem_u32(const void* p) {
    uint32_t a;
    asm("{ .reg .u64 t; cvta.to.shared.u64 t, %1; cvt.u32.u64 %0, t; }"
        : "=r"(a) : "l"(p));
    return a;
}
__device__ __forceinline__ uint32_t pack_f16x2(float x, float y) {
    __half2 h = __floats2half2_rn(x, y);
    return *(uint32_t*)&h;
}
__device__ __forceinline__ void split_pack_f16(float x, float y,
                                               uint32_t& hi, uint32_t& lo) {
    __half2 h = __floats2half2_rn(x, y);
    float2 b = __half22float2(h);
    __half2 l = __floats2half2_rn(x - b.x, y - b.y);
    hi = *(uint32_t*)&h;
    lo = *(uint32_t*)&l;
}
__device__ __forceinline__ void ldsm4(uint32_t (&r)[4], uint32_t a) {
    asm volatile("ldmatrix.sync.aligned.m8n8.x4.shared.b16 {%0,%1,%2,%3}, [%4];"
        : "=r"(r[0]), "=r"(r[1]), "=r"(r[2]), "=r"(r[3]) : "r"(a));
}
__device__ __forceinline__ void ldsm4t(uint32_t (&r)[4], uint32_t a) {
    asm volatile("ldmatrix.sync.aligned.m8n8.x4.trans.shared.b16 {%0,%1,%2,%3}, [%4];"
        : "=r"(r[0]), "=r"(r[1]), "=r"(r[2]), "=r"(r[3]) : "r"(a));
}
__device__ __forceinline__ void mma_f16(float (&c)[4], const uint32_t (&a)[4],
                                        uint32_t b0, uint32_t b1) {
    asm volatile("mma.sync.aligned.m16n8k16.row.col.f32.f16.f16.f32 "
        "{%0,%1,%2,%3}, {%4,%5,%6,%7}, {%8,%9}, {%0,%1,%2,%3};"
        : "+f"(c[0]), "+f"(c[1]), "+f"(c[2]), "+f"(c[3])
        : "r"(a[0]), "r"(a[1]), "r"(a[2]), "r"(a[3]), "r"(b0), "r"(b1));
}
__device__ __forceinline__ void cp16(uint32_t dst, const void* src) {
    asm volatile("cp.async.cg.shared.global [%0], [%1], 16;" :: "r"(dst), "l"(src));
}
#define CP_COMMIT() asm volatile("cp.async.commit_group;" ::: "memory")
#define CP_WAIT(n)  asm volatile("cp.async.wait_group %0;" :: "n"(n) : "memory")

// ---------------------------------------------------------------------------
// Fused prep: hs hi/lo split + all 4 weight converts + rope table.
// ---------------------------------------------------------------------------
#define HS_T  (TSEQ * HID / 8)
#define WQ_T  (HID * NH * DH / 8)
#define WK_T  (HID * NKV * DH / 8)
#define WV_T  (HID * NKV * DH / 8)
#define WO_T  (NH * DH * HID / 8)
#define TAB_T (TSEQ * 64)
#define PREP_TOT (HS_T + WQ_T + WK_T + WV_T + WO_T + TAB_T)

__global__ void prep_kernel(const int* __restrict__ positions,
                            const float4* __restrict__ hs,
                            const float4* __restrict__ wq,
                            const float4* __restrict__ wk,
                            const float4* __restrict__ wv,
                            const float4* __restrict__ wo)
{
    int i = blockIdx.x * blockDim.x + threadIdx.x;
    if (i >= PREP_TOT) return;
    int j = i;
    if (j < HS_T) {
        float4 v0 = hs[j * 2];
        float4 v1 = hs[j * 2 + 1];
        uint32_t h0, l0, h1, l1, h2, l2, h3, l3;
        split_pack_f16(v0.x, v0.y, h0, l0);
        split_pack_f16(v0.z, v0.w, h1, l1);
        split_pack_f16(v1.x, v1.y, h2, l2);
        split_pack_f16(v1.z, v1.w, h3, l3);
        ((uint4*)g_hsh)[j] = make_uint4(h0, h1, h2, h3);
        ((uint4*)g_hsl)[j] = make_uint4(l0, l1, l2, l3);
        return;
    }
    j -= HS_T;
    const float4* src;
    uint4* dst;
    if (j < WQ_T)                 { src = wq; dst = (uint4*)g_wq; }
    else if ((j -= WQ_T) < WK_T)  { src = wk; dst = (uint4*)g_wk; }
    else if ((j -= WK_T) < WV_T)  { src = wv; dst = (uint4*)g_wv; }
    else if ((j -= WV_T) < WO_T)  { src = wo; dst = (uint4*)g_wo; }
    else {
        j -= WO_T;                 // rope table entry
        int d = j & 63, t = j >> 6;
        float pos = (float)positions[t];
        float inv_freq = powf(1.0e6f, -(float)d * (1.0f / 64.0f));
        float s, c;
        sincosf(pos * inv_freq, &s, &c);
        g_tab[j] = make_float2(c, s);
        return;
    }
    float4 v0 = src[j * 2];
    float4 v1 = src[j * 2 + 1];
    dst[j] = make_uint4(pack_f16x2(v0.x, v0.y), pack_f16x2(v0.z, v0.w),
                        pack_f16x2(v1.x, v1.y), pack_f16x2(v1.z, v1.w));
}

// ---------------------------------------------------------------------------
// Core GEMM tile (R9-proven config): C[bm:+128, bn:+128] = A@B (+bias).
// A fp16 hi/lo split, B plain fp16. K-chunk 64, 2-stage cp.async.
// 256 threads (4Mx2N warps), 2 CTAs/SM.
// ---------------------------------------------------------------------------
#define TG_AT 18432u            // A tile [128][144B]
#define TG_BT 17408u            // B tile [64][272B]
#define TG_BUF (2u * TG_AT + TG_BT)         // 54272
#define TG_SMEM (2u * TG_BUF)               // 108544

__device__ __forceinline__ void gemm_tile(
    const __half* __restrict__ Ah, const __half* __restrict__ Al,
    const __half* __restrict__ B,
    const float* __restrict__ bias, float* __restrict__ C,
    __half* __restrict__ Ch,
    int N, int K, int bm, int bn, char* sm)
{
    const uint32_t sb = smem_u32(sm);
    const int tid  = threadIdx.x;
    const int wid  = tid >> 5;
    const int lane = tid & 31;
    const int wm = (wid >> 1) << 5;
    const int wn = (wid & 1) << 6;

    auto issue = [&](int k0, int buf) {
        const uint32_t base = sb + (uint32_t)buf * TG_BUF;
        #pragma unroll
        for (int i = 0; i < 4; i++) {
            int idx = tid + i * 256;
            int ar = idx >> 3, ac = idx & 7;
            const size_t aoff = (size_t)(bm + ar) * K + k0 + ac * 8;
            cp16(base + (uint32_t)(ar * 144 + ac * 16), Ah + aoff);
            cp16(base + TG_AT + (uint32_t)(ar * 144 + ac * 16), Al + aoff);
            int br = idx >> 4, bc = idx & 15;
            const size_t boff = (size_t)(k0 + br) * N + bn + bc * 8;
            cp16(base + 2u * TG_AT + (uint32_t)(br * 272 + bc * 16), B + boff);
        }
    };

    float acc[2][8][4];
    #pragma unroll
    for (int mi = 0; mi < 2; mi++)
        #pragma unroll
        for (int j = 0; j < 8; j++)
            #pragma unroll
            for (int q = 0; q < 4; q++) acc[mi][j][q] = 0.f;

    const int NC = K >> 6;
    issue(0, 0); CP_COMMIT();

    for (int c = 0; c < NC; c++) {
        if (c + 1 < NC) { issue((c + 1) << 6, (c + 1) & 1); CP_COMMIT(); CP_WAIT(1); }
        else            { CP_WAIT(0); }
        __syncthreads();

        const uint32_t base = sb + (uint32_t)(c & 1) * TG_BUF;
        #pragma unroll
        for (int ks = 0; ks < 4; ks++) {
            uint32_t afh[2][4], afl[2][4];
            #pragma unroll
            for (int mi = 0; mi < 2; mi++) {
                uint32_t ro = base + (uint32_t)((wm + mi * 16 + (lane & 15)) * 144
                                                + ks * 32 + (lane >> 4) * 16);
                ldsm4(afh[mi], ro);
                ldsm4(afl[mi], ro + TG_AT);
            }
            uint32_t bf[4][4];
            const uint32_t kro = base + 2u * TG_AT
                + (uint32_t)((ks * 16 + (lane & 15)) * 272 + (lane >> 4) * 16);
            #pragma unroll
            for (int nb = 0; nb < 4; nb++)
                ldsm4t(bf[nb], kro + (uint32_t)((wn + nb * 16) * 2));
            #pragma unroll
            for (int mi = 0; mi < 2; mi++)
                #pragma unroll
                for (int nb = 0; nb < 4; nb++)
                    #pragma unroll
                    for (int hh = 0; hh < 2; hh++) {
                        float (&cc)[4] = acc[mi][nb * 2 + hh];
                        mma_f16(cc, afh[mi], bf[nb][2 * hh], bf[nb][2 * hh + 1]);
                        mma_f16(cc, afl[mi], bf[nb][2 * hh], bf[nb][2 * hh + 1]);
                    }
        }
        __syncthreads();   // all warps done with this buffer before re-fill
    }

    // epilogue
    const int r0 = lane >> 2;
    const int c0 = (lane & 3) << 1;
    #pragma unroll
    for (int mi = 0; mi < 2; mi++) {
        #pragma unroll
        for (int j = 0; j < 8; j++) {
            const int col = bn + wn + j * 8 + c0;
            float bias0 = 0.f, bias1 = 0.f;
            if (bias != nullptr) { bias0 = bias[col]; bias1 = bias[col + 1]; }
            const int row_a = bm + wm + mi * 16 + r0;
            const int row_b = row_a + 8;
            float va0 = acc[mi][j][0] + bias0, va1 = acc[mi][j][1] + bias1;
            float vb0 = acc[mi][j][2] + bias0, vb1 = acc[mi][j][3] + bias1;
            float* Ca = C + (size_t)row_a * N + col;
            float* Cb = C + (size_t)row_b * N + col;
            Ca[0] = va0; Ca[1] = va1;
            Cb[0] = vb0; Cb[1] = vb1;
            if (Ch != nullptr) {
                *(uint32_t*)(Ch + (size_t)row_a * N + col) = pack_f16x2(va0, va1);
                *(uint32_t*)(Ch + (size_t)row_b * N + col) = pack_f16x2(vb0, vb1);
            }
        }
    }
}

// Fused QKV projection: grid (48, 16). bx<32 -> Q, [32,40) -> K, [40,48) -> V.
__global__ __launch_bounds__(256, 2) void tgemm_qkv(
    const float* __restrict__ bq, const float* __restrict__ bk,
    const float* __restrict__ bv,
    float* __restrict__ qbuf, float* __restrict__ kout, float* __restrict__ vout)
{
    extern __shared__ char sm[];
    const int bx = blockIdx.x;
    const int bm = blockIdx.y << 7;
    if (bx < 32) {
        gemm_tile(g_hsh, g_hsl, g_wq, bq, qbuf, nullptr,
                  NH * DH, HID, bm, bx << 7, sm);
    } else if (bx < 40) {
        gemm_tile(g_hsh, g_hsl, g_wk, bk, kout, nullptr,
                  NKV * DH, HID, bm, (bx - 32) << 7, sm);
    } else {
        gemm_tile(g_hsh, g_hsl, g_wv, bv, vout, g_v,
                  NKV * DH, HID, bm, (bx - 40) << 7, sm);
    }
}

// O projection: grid (32, 16).
__global__ __launch_bounds__(256, 2) void tgemm_o(float* __restrict__ out)
{
    extern __shared__ char sm[];
    gemm_tile(g_ah, g_al, g_wo, nullptr, out, nullptr,
              HID, NH * DH, blockIdx.y << 7, blockIdx.x << 7, sm);
}

// ---------------------------------------------------------------------------
// Fused rope: first TSEQ*NH*64 indices -> Q path, rest -> K path.
// ---------------------------------------------------------------------------
#define RQ_T (TSEQ * NH * 64)
#define RK_T (TSEQ * NKV * 64)

__global__ void rope_kernel(const float* __restrict__ q, float* __restrict__ k)
{
    int i = blockIdx.x * blockDim.x + threadIdx.x;
    if (i >= RQ_T + RK_T) return;
    if (i < RQ_T) {
        int d = i & 63;
        int rest = i >> 6;
        int hh = rest % NH;
        int t  = rest / NH;
        const float scale = 0.08838834764831843f;
        float2 cs = g_tab[t * 64 + d];
        size_t base = (size_t)t * (NH * DH) + (size_t)hh * DH;
        float x1 = q[base + d];
        float x2 = q[base + d + 64];
        float y1 = (x1 * cs.x - x2 * cs.y) * scale;
        float y2 = (x2 * cs.x + x1 * cs.y) * scale;
        __half h1 = __float2half_rn(y1);
        __half h2 = __float2half_rn(y2);
        g_qh[base + d]      = h1;
        g_ql[base + d]      = __float2half_rn(y1 - __half2float(h1));
        g_qh[base + d + 64] = h2;
        g_ql[base + d + 64] = __float2half_rn(y2 - __half2float(h2));
    } else {
        int j = i - RQ_T;
        int d = j & 63;
        int rest = j >> 6;
        int hh = rest % NKV;
        int t  = rest / NKV;
        float2 cs = g_tab[t * 64 + d];
        size_t base = (size_t)t * (NKV * DH) + (size_t)hh * DH;
        float x1 = k[base + d];
        float x2 = k[base + d + 64];
        float y1 = x1 * cs.x - x2 * cs.y;
        float y2 = x2 * cs.x + x1 * cs.y;
        k[base + d]      = y1;
        k[base + d + 64] = y2;
        g_ktr[((size_t)hh * DH + d) * TSEQ + t]      = __float2half_rn(y1);
        g_ktr[((size_t)hh * DH + d + 64) * TSEQ + t] = __float2half_rn(y2);
    }
}

// ---------------------------------------------------------------------------
// MMA flash attention: 128 q-rows/CTA, 256 threads. Q fp16 hi/lo (pre-scaled),
// K/V plain fp16 (K pre-transposed), P split x2. cp.async 2-stage KV.
// Grid (NH, T/128); m0 reversed for wave balance. (unchanged, proven)
// ---------------------------------------------------------------------------
#define A2_Q  34816u    // [128][272B]
#define A2_KT 18432u    // [128][144B]
#define A2_V  17408u    // [64][272B]
#define O_QH 0u
#define O_QL A2_Q
#define O_KV0 (2u * A2_Q)
#define KV_BUF (A2_KT + A2_V)
#define A2_SMEM (2u * A2_Q + 2u * KV_BUF)   // 141312

__global__ __launch_bounds__(256, 1) void attn_mma(
    __half* __restrict__ oh, __half* __restrict__ ol)
{
    extern __shared__ char sm[];
    const uint32_t sb = smem_u32(sm);
    const int h  = blockIdx.x;
    const int m0 = (int)(gridDim.y - 1 - blockIdx.y) << 7;
    const int kvh = h / GRP;
    const int tid = threadIdx.x;
    const int wid = tid >> 5;
    const int lane = tid & 31;
    const int wm = wid << 4;
    const int gID = lane >> 2;
    const int tig = lane & 3;

    const __half* ktr_h = g_ktr + (size_t)kvh * DH * TSEQ;

    auto issue_kv = [&](int n0, int b) {
        const uint32_t kb = sb + O_KV0 + (uint32_t)b * KV_BUF;
        #pragma unroll
        for (int i = 0; i < 4; i++) {
            int idx = tid + i * 256;
            int dr = idx >> 3, dc = idx & 7;
            cp16(kb + (uint32_t)(dr * 144 + dc * 16),
                 ktr_h + (size_t)dr * TSEQ + n0 + dc * 8);
            int vr = idx >> 4, vc = idx & 15;
            cp16(kb + A2_KT + (uint32_t)(vr * 272 + vc * 16),
                 g_v + (size_t)(n0 + vr) * (NKV * DH) + (size_t)kvh * DH + vc * 8);
        }
    };

    // load Q tile (128 x 128) hi/lo
    #pragma unroll
    for (int i = 0; i < 8; i++) {
        int idx = tid + i * 256;
        int r = idx >> 4, ch = idx & 15;
        const size_t go = (size_t)(m0 + r) * (NH * DH) + (size_t)h * DH + ch * 8;
        *(uint4*)(sm + O_QH + r * 272 + ch * 16) = *(const uint4*)(g_qh + go);
        *(uint4*)(sm + O_QL + r * 272 + ch * 16) = *(const uint4*)(g_ql + go);
    }

    float oacc[16][4];
    #pragma unroll
    for (int j = 0; j < 16; j++)
        #pragma unroll
        for (int q = 0; q < 4; q++) oacc[j][q] = 0.f;
    float m_run0 = -1e30f, m_run1 = -1e30f, l_run0 = 0.f, l_run1 = 0.f;

    const int row0 = m0 + wm + gID;
    const int row1 = row0 + 8;
    const int warp_max_row = m0 + wm + 15;

    const int nblocks = (m0 >> 6) + 2;
    issue_kv(0, 0); CP_COMMIT();

    for (int blk = 0; blk < nblocks; blk++) {
        const int n0 = blk << 6;
        const bool more = (blk + 1 < nblocks);
        if (more) { issue_kv((blk + 1) << 6, (blk + 1) & 1); CP_COMMIT(); CP_WAIT(1); }
        else      { CP_WAIT(0); }
        __syncthreads();

        if (n0 <= warp_max_row) {
            const uint32_t kb = sb + O_KV0 + (uint32_t)(blk & 1) * KV_BUF;

            // ---- S = Q K^T (2 products) ----
            float sacc[8][4];
            #pragma unroll
            for (int j = 0; j < 8; j++)
                #pragma unroll
                for (int q = 0; q < 4; q++) sacc[j][q] = 0.f;

            #pragma unroll
            for (int ks = 0; ks < 8; ks++) {
                uint32_t aH[4], aL[4];
                uint32_t ro = sb + O_QH + (uint32_t)((wm + (lane & 15)) * 272
                                                     + ks * 32 + (lane >> 4) * 16);
                ldsm4(aH, ro);
                ldsm4(aL, ro + A2_Q);
                const uint32_t kro = kb
                    + (uint32_t)((ks * 16 + (lane & 15)) * 144 + (lane >> 4) * 16);
                #pragma unroll
                for (int nb = 0; nb < 4; nb++) {
                    uint32_t bk4[4];
                    ldsm4t(bk4, kro + (uint32_t)(nb * 32));
                    #pragma unroll
                    for (int hh = 0; hh < 2; hh++) {
                        float (&cc)[4] = sacc[nb * 2 + hh];
                        mma_f16(cc, aH, bk4[2 * hh], bk4[2 * hh + 1]);
                        mma_f16(cc, aL, bk4[2 * hh], bk4[2 * hh + 1]);
                    }
                }
            }

            // ---- online softmax ----
            float mx0 = -1e30f, mx1 = -1e30f;
            #pragma unroll
            for (int nb = 0; nb < 8; nb++) {
                #pragma unroll
                for (int j = 0; j < 2; j++) {
                    const int col = n0 + nb * 8 + tig * 2 + j;
                    float s0 = sacc[nb][j];
                    float s1 = sacc[nb][2 + j];
                    if (col > row0) s0 = -1e30f;
                    if (col > row1) s1 = -1e30f;
                    sacc[nb][j] = s0;
                    sacc[nb][2 + j] = s1;
                    mx0 = fmaxf(mx0, s0);
                    mx1 = fmaxf(mx1, s1);
                }
            }
            #pragma unroll
            for (int off = 1; off <= 2; off <<= 1) {
                mx0 = fmaxf(mx0, __shfl_xor_sync(0xffffffffu, mx0, off));
                mx1 = fmaxf(mx1, __shfl_xor_sync(0xffffffffu, mx1, off));
            }
            float mn0 = fmaxf(m_run0, mx0);
            float mn1 = fmaxf(m_run1, mx1);
            float cf0 = __expf(m_run0 - mn0);
            float cf1 = __expf(m_run1 - mn1);
            m_run0 = mn0; m_run1 = mn1;
            float su0 = 0.f, su1 = 0.f;
            #pragma unroll
            for (int nb = 0; nb < 8; nb++) {
                #pragma unroll
                for (int j = 0; j < 2; j++) {
                    float p0 = __expf(sacc[nb][j] - mn0);
                    float p1 = __expf(sacc[nb][2 + j] - mn1);
                    sacc[nb][j] = p0;
                    sacc[nb][2 + j] = p1;
                    su0 += p0;
                    su1 += p1;
                }
            }
            #pragma unroll
            for (int off = 1; off <= 2; off <<= 1) {
                su0 += __shfl_xor_sync(0xffffffffu, su0, off);
                su1 += __shfl_xor_sync(0xffffffffu, su1, off);
            }
            l_run0 = l_run0 * cf0 + su0;
            l_run1 = l_run1 * cf1 + su1;
            #pragma unroll
            for (int j = 0; j < 16; j++) {
                oacc[j][0] *= cf0;
                oacc[j][1] *= cf0;
                oacc[j][2] *= cf1;
                oacc[j][3] *= cf1;
            }

            // ---- O += P V (2 products; P split register-direct) ----
            #pragma unroll
            for (int ks = 0; ks < 4; ks++) {
                uint32_t ph[4], pl[4];
                split_pack_f16(sacc[2 * ks][0],     sacc[2 * ks][1],     ph[0], pl[0]);
                split_pack_f16(sacc[2 * ks][2],     sacc[2 * ks][3],     ph[1], pl[1]);
                split_pack_f16(sacc[2 * ks + 1][0], sacc[2 * ks + 1][1], ph[2], pl[2]);
                split_pack_f16(sacc[2 * ks + 1][2], sacc[2 * ks + 1][3], ph[3], pl[3]);
                const uint32_t vro = kb + A2_KT
                    + (uint32_t)((ks * 16 + (lane & 15)) * 272 + (lane >> 4) * 16);
                #pragma unroll
                for (int nbv = 0; nbv < 8; nbv++) {
                    uint32_t vb4[4];
                    ldsm4t(vb4, vro + (uint32_t)(nbv * 32));
                    #pragma unroll
                    for (int hh = 0; hh < 2; hh++) {
                        float (&cc)[4] = oacc[nbv * 2 + hh];
                        mma_f16(cc, ph, vb4[2 * hh], vb4[2 * hh + 1]);
                        mma_f16(cc, pl, vb4[2 * hh], vb4[2 * hh + 1]);
                    }
                }
            }
        }
        __syncthreads();
    }

    // epilogue: write fp16 hi/lo split of normalized output
    const float inv0 = 1.0f / l_run0;
    const float inv1 = 1.0f / l_run1;
    #pragma unroll
    for (int onb = 0; onb < 16; onb++) {
        const int col = h * DH + onb * 8 + tig * 2;
        const size_t i0 = (size_t)row0 * (NH * DH) + col;
        const size_t i1 = (size_t)row1 * (NH * DH) + col;
        uint32_t hh_, ll_;
        split_pack_f16(oacc[onb][0] * inv0, oacc[onb][1] * inv0, hh_, ll_);
        *(uint32_t*)(oh + i0) = hh_;
        *(uint32_t*)(ol + i0) = ll_;
        split_pack_f16(oacc[onb][2] * inv1, oacc[onb][3] * inv1, hh_, ll_);
        *(uint32_t*)(oh + i1) = hh_;
        *(uint32_t*)(ol + i1) = ll_;
    }
}

// ---------------------------------------------------------------------------
extern "C" void kernel_launch(void* const* d_in, const int* in_sizes, int n_in,
                              void* d_out, int out_size)
{
    const int*   positions = (const int*)d_in[0];
    const float* hs = (const float*)d_in[1];
    const float* Wq = (const float*)d_in[2];
    const float* bq = (const float*)d_in[3];
    const float* Wk = (const float*)d_in[4];
    const float* bk = (const float*)d_in[5];
    const float* Wv = (const float*)d_in[6];
    const float* bv = (const float*)d_in[7];
    const float* Wo = (const float*)d_in[8];

    float* out  = (float*)d_out;
    float* kout = out + (size_t)TSEQ * HID;
    float* vout = kout + (size_t)TSEQ * NKV * DH;

    float *qbuf;
    __half *aah, *aal;
    cudaGetSymbolAddress((void**)&qbuf, g_q);
    cudaGetSymbolAddress((void**)&aah, g_ah);
    cudaGetSymbolAddress((void**)&aal, g_al);

    cudaFuncSetAttribute(tgemm_qkv, cudaFuncAttributeMaxDynamicSharedMemorySize, (int)TG_SMEM);
    cudaFuncSetAttribute(tgemm_o, cudaFuncAttributeMaxDynamicSharedMemorySize, (int)TG_SMEM);
    cudaFuncSetAttribute(attn_mma, cudaFuncAttributeMaxDynamicSharedMemorySize, (int)A2_SMEM);

    // 1. fused prep (hs split, weight converts, rope table)
    prep_kernel<<<(PREP_TOT + 255) / 256, 256>>>(
        positions, (const float4*)hs, (const float4*)Wq, (const float4*)Wk,
        (const float4*)Wv, (const float4*)Wo);

    // 2. fused QKV projection
    tgemm_qkv<<<dim3(48, 16), 256, TG_SMEM>>>(bq, bk, bv, qbuf, kout, vout);

    // 3. fused rope
    rope_kernel<<<(RQ_T + RK_T + 255) / 256, 256>>>(qbuf, kout);

    // 4. attention
    attn_mma<<<dim3(NH, TSEQ / 128), 256, A2_SMEM>>>(aah, aal);

    // 5. O projection
    tgemm_o<<<dim3(32, 16), 256, TG_SMEM>>>(out);
}

// round 13
// speedup vs baseline: 1.0708x; 1.0093x over previous
#include <cuda_runtime.h>
#include <cuda_fp16.h>
#include <math.h>
#include <stdint.h>

#define TSEQ 2048
#define HID  4096
#define NH   32
#define NKV  8
#define DH   128
#define GRP  (NH / NKV)

// ---------------------------------------------------------------------------
// Scratch (allocation-free rule: __device__ globals)
// ---------------------------------------------------------------------------
__device__ float g_q[(size_t)TSEQ * NH * DH];            // fp32 Q (pre-rope)
__device__ float2 g_tab[(size_t)TSEQ * 64];              // rope (cos,sin)
__device__ __half g_hsh[(size_t)TSEQ * HID], g_hsl[(size_t)TSEQ * HID];
__device__ __half g_wq[(size_t)HID * NH * DH];
__device__ __half g_wk[(size_t)HID * NKV * DH];
__device__ __half g_wv[(size_t)HID * NKV * DH];
__device__ __half g_wo[(size_t)NH * DH * HID];
__device__ __half g_qh[(size_t)TSEQ * NH * DH], g_ql[(size_t)TSEQ * NH * DH];
__device__ __half g_ktr[(size_t)NKV * DH * TSEQ];        // K transposed [h][d][t]
__device__ __half g_v[(size_t)TSEQ * NKV * DH];
__device__ __half g_ah[(size_t)TSEQ * NH * DH], g_al[(size_t)TSEQ * NH * DH];

// ---------------------------------------------------------------------------
// helpers
// ---------------------------------------------------------------------------
__device__ __forceinline__ uint32_t smem_u32(const void* p) {
    uint32_t a;
    asm("{ .reg .u64 t; cvta.to.shared.u64 t, %1; cvt.u32.u64 %0, t; }"
        : "=r"(a) : "l"(p));
    return a;
}
__device__ __forceinline__ uint32_t pack_f16x2(float x, float y) {
    __half2 h = __floats2half2_rn(x, y);
    return *(uint32_t*)&h;
}
__device__ __forceinline__ void split_pack_f16(float x, float y,
                                               uint32_t& hi, uint32_t& lo) {
    __half2 h = __floats2half2_rn(x, y);
    float2 b = __half22float2(h);
    __half2 l = __floats2half2_rn(x - b.x, y - b.y);
    hi = *(uint32_t*)&h;
    lo = *(uint32_t*)&l;
}
__device__ __forceinline__ void ldsm4(uint32_t (&r)[4], uint32_t a) {
    asm volatile("ldmatrix.sync.aligned.m8n8.x4.shared.b16 {%0,%1,%2,%3}, [%4];"
        : "=r"(r[0]), "=r"(r[1]), "=r"(r[2]), "=r"(r[3]) : "r"(a));
}
__device__ __forceinline__ void ldsm4t(uint32_t (&r)[4], uint32_t a) {
    asm volatile("ldmatrix.sync.aligned.m8n8.x4.trans.shared.b16 {%0,%1,%2,%3}, [%4];"
        : "=r"(r[0]), "=r"(r[1]), "=r"(r[2]), "=r"(r[3]) : "r"(a));
}
__device__ __forceinline__ void mma_f16(float (&c)[4], const uint32_t (&a)[4],
                                        uint32_t b0, uint32_t b1) {
    asm volatile("mma.sync.aligned.m16n8k16.row.col.f32.f16.f16.f32 "
        "{%0,%1,%2,%3}, {%4,%5,%6,%7}, {%8,%9}, {%0,%1,%2,%3};"
        : "+f"(c[0]), "+f"(c[1]), "+f"(c[2]), "+f"(c[3])
        : "r"(a[0]), "r"(a[1]), "r"(a[2]), "r"(a[3]), "r"(b0), "r"(b1));
}
__device__ __forceinline__ void cp16(uint32_t dst, const void* src) {
    asm volatile("cp.async.cg.shared.global [%0], [%1], 16;" :: "r"(dst), "l"(src));
}
#define CP_COMMIT() asm volatile("cp.async.commit_group;" ::: "memory")
#define CP_WAIT(n)  asm volatile("cp.async.wait_group %0;" :: "n"(n) : "memory")

// ---------------------------------------------------------------------------
// Fused prep: hs hi/lo split + all 4 weight converts + rope table.
// ---------------------------------------------------------------------------
#define HS_T  (TSEQ * HID / 8)
#define WQ_T  (HID * NH * DH / 8)
#define WK_T  (HID * NKV * DH / 8)
#define WV_T  (HID * NKV * DH / 8)
#define WO_T  (NH * DH * HID / 8)
#define TAB_T (TSEQ * 64)
#define PREP_TOT (HS_T + WQ_T + WK_T + WV_T + WO_T + TAB_T)

__global__ void prep_kernel(const int* __restrict__ positions,
                            const float4* __restrict__ hs,
                            const float4* __restrict__ wq,
                            const float4* __restrict__ wk,
                            const float4* __restrict__ wv,
                            const float4* __restrict__ wo)
{
    int i = blockIdx.x * blockDim.x + threadIdx.x;
    if (i >= PREP_TOT) return;
    int j = i;
    if (j < HS_T) {
        float4 v0 = hs[j * 2];
        float4 v1 = hs[j * 2 + 1];
        uint32_t h0, l0, h1, l1, h2, l2, h3, l3;
        split_pack_f16(v0.x, v0.y, h0, l0);
        split_pack_f16(v0.z, v0.w, h1, l1);
        split_pack_f16(v1.x, v1.y, h2, l2);
        split_pack_f16(v1.z, v1.w, h3, l3);
        ((uint4*)g_hsh)[j] = make_uint4(h0, h1, h2, h3);
        ((uint4*)g_hsl)[j] = make_uint4(l0, l1, l2, l3);
        return;
    }
    j -= HS_T;
    const float4* src;
    uint4* dst;
    if (j < WQ_T)                 { src = wq; dst = (uint4*)g_wq; }
    else if ((j -= WQ_T) < WK_T)  { src = wk; dst = (uint4*)g_wk; }
    else if ((j -= WK_T) < WV_T)  { src = wv; dst = (uint4*)g_wv; }
    else if ((j -= WV_T) < WO_T)  { src = wo; dst = (uint4*)g_wo; }
    else {
        j -= WO_T;                 // rope table entry
        int d = j & 63, t = j >> 6;
        float pos = (float)positions[t];
        float inv_freq = powf(1.0e6f, -(float)d * (1.0f / 64.0f));
        float s, c;
        sincosf(pos * inv_freq, &s, &c);
        g_tab[j] = make_float2(c, s);
        return;
    }
    float4 v0 = src[j * 2];
    float4 v1 = src[j * 2 + 1];
    dst[j] = make_uint4(pack_f16x2(v0.x, v0.y), pack_f16x2(v0.z, v0.w),
                        pack_f16x2(v1.x, v1.y), pack_f16x2(v1.z, v1.w));
}

// ---------------------------------------------------------------------------
// Core GEMM tile: C[bm:+128, bn:+128] = A@B (+bias). A fp16 hi/lo split,
// B plain fp16. K-chunk 64, 2-stage cp.async, ONE sync per chunk
// (wait -> sync -> issue -> compute). 256 threads (4Mx2N warps), 2 CTAs/SM.
// ---------------------------------------------------------------------------
#define TG_AT 18432u            // A tile [128][144B]
#define TG_BT 17408u            // B tile [64][272B]
#define TG_BUF (2u * TG_AT + TG_BT)         // 54272
#define TG_SMEM (2u * TG_BUF)               // 108544

__device__ __forceinline__ void gemm_tile(
    const __half* __restrict__ Ah, const __half* __restrict__ Al,
    const __half* __restrict__ B,
    const float* __restrict__ bias, float* __restrict__ C,
    __half* __restrict__ Ch,
    int N, int K, int bm, int bn, char* sm)
{
    const uint32_t sb = smem_u32(sm);
    const int tid  = threadIdx.x;
    const int wid  = tid >> 5;
    const int lane = tid & 31;
    const int wm = (wid >> 1) << 5;
    const int wn = (wid & 1) << 6;

    auto issue = [&](int k0, int buf) {
        const uint32_t base = sb + (uint32_t)buf * TG_BUF;
        #pragma unroll
        for (int i = 0; i < 4; i++) {
            int idx = tid + i * 256;
            int ar = idx >> 3, ac = idx & 7;
            const size_t aoff = (size_t)(bm + ar) * K + k0 + ac * 8;
            cp16(base + (uint32_t)(ar * 144 + ac * 16), Ah + aoff);
            cp16(base + TG_AT + (uint32_t)(ar * 144 + ac * 16), Al + aoff);
            int br = idx >> 4, bc = idx & 15;
            const size_t boff = (size_t)(k0 + br) * N + bn + bc * 8;
            cp16(base + 2u * TG_AT + (uint32_t)(br * 272 + bc * 16), B + boff);
        }
    };

    float acc[2][8][4];
    #pragma unroll
    for (int mi = 0; mi < 2; mi++)
        #pragma unroll
        for (int j = 0; j < 8; j++)
            #pragma unroll
            for (int q = 0; q < 4; q++) acc[mi][j][q] = 0.f;

    const int NC = K >> 6;
    issue(0, 0); CP_COMMIT();

    for (int c = 0; c < NC; c++) {
        CP_WAIT(0);          // chunk c landed (it was the only pending group)
        __syncthreads();     // data visible + all warps done with prev buffer
        if (c + 1 < NC) { issue((c + 1) << 6, (c + 1) & 1); CP_COMMIT(); }

        const uint32_t base = sb + (uint32_t)(c & 1) * TG_BUF;
        #pragma unroll
        for (int ks = 0; ks < 4; ks++) {
            uint32_t afh[2][4], afl[2][4];
            #pragma unroll
            for (int mi = 0; mi < 2; mi++) {
                uint32_t ro = base + (uint32_t)((wm + mi * 16 + (lane & 15)) * 144
                                                + ks * 32 + (lane >> 4) * 16);
                ldsm4(afh[mi], ro);
                ldsm4(afl[mi], ro + TG_AT);
            }
            uint32_t bf[4][4];
            const uint32_t kro = base + 2u * TG_AT
                + (uint32_t)((ks * 16 + (lane & 15)) * 272 + (lane >> 4) * 16);
            #pragma unroll
            for (int nb = 0; nb < 4; nb++)
                ldsm4t(bf[nb], kro + (uint32_t)((wn + nb * 16) * 2));
            #pragma unroll
            for (int mi = 0; mi < 2; mi++)
                #pragma unroll
                for (int nb = 0; nb < 4; nb++)
                    #pragma unroll
                    for (int hh = 0; hh < 2; hh++) {
                        float (&cc)[4] = acc[mi][nb * 2 + hh];
                        mma_f16(cc, afh[mi], bf[nb][2 * hh], bf[nb][2 * hh + 1]);
                        mma_f16(cc, afl[mi], bf[nb][2 * hh], bf[nb][2 * hh + 1]);
                    }
        }
    }

    // epilogue (register-only inputs; no further smem hazards)
    const int r0 = lane >> 2;
    const int c0 = (lane & 3) << 1;
    #pragma unroll
    for (int mi = 0; mi < 2; mi++) {
        #pragma unroll
        for (int j = 0; j < 8; j++) {
            const int col = bn + wn + j * 8 + c0;
            float bias0 = 0.f, bias1 = 0.f;
            if (bias != nullptr) { bias0 = bias[col]; bias1 = bias[col + 1]; }
            const int row_a = bm + wm + mi * 16 + r0;
            const int row_b = row_a + 8;
            float va0 = acc[mi][j][0] + bias0, va1 = acc[mi][j][1] + bias1;
            float vb0 = acc[mi][j][2] + bias0, vb1 = acc[mi][j][3] + bias1;
            float* Ca = C + (size_t)row_a * N + col;
            float* Cb = C + (size_t)row_b * N + col;
            Ca[0] = va0; Ca[1] = va1;
            Cb[0] = vb0; Cb[1] = vb1;
            if (Ch != nullptr) {
                *(uint32_t*)(Ch + (size_t)row_a * N + col) = pack_f16x2(va0, va1);
                *(uint32_t*)(Ch + (size_t)row_b * N + col) = pack_f16x2(vb0, vb1);
            }
        }
    }
}

// Fused QKV projection: grid (48, 16). bx<32 -> Q, [32,40) -> K, [40,48) -> V.
__global__ __launch_bounds__(256, 2) void tgemm_qkv(
    const float* __restrict__ bq, const float* __restrict__ bk,
    const float* __restrict__ bv,
    float* __restrict__ qbuf, float* __restrict__ kout, float* __restrict__ vout)
{
    extern __shared__ char sm[];
    const int bx = blockIdx.x;
    const int bm = blockIdx.y << 7;
    if (bx < 32) {
        gemm_tile(g_hsh, g_hsl, g_wq, bq, qbuf, nullptr,
                  NH * DH, HID, bm, bx << 7, sm);
    } else if (bx < 40) {
        gemm_tile(g_hsh, g_hsl, g_wk, bk, kout, nullptr,
                  NKV * DH, HID, bm, (bx - 32) << 7, sm);
    } else {
        gemm_tile(g_hsh, g_hsl, g_wv, bv, vout, g_v,
                  NKV * DH, HID, bm, (bx - 40) << 7, sm);
    }
}

// O projection: grid (32, 16).
__global__ __launch_bounds__(256, 2) void tgemm_o(float* __restrict__ out)
{
    extern __shared__ char sm[];
    gemm_tile(g_ah, g_al, g_wo, nullptr, out, nullptr,
              HID, NH * DH, blockIdx.y << 7, blockIdx.x << 7, sm);
}

// ---------------------------------------------------------------------------
// Fused rope: first TSEQ*NH*64 indices -> Q path, rest -> K path.
// ---------------------------------------------------------------------------
#define RQ_T (TSEQ * NH * 64)
#define RK_T (TSEQ * NKV * 64)

__global__ void rope_kernel(const float* __restrict__ q, float* __restrict__ k)
{
    int i = blockIdx.x * blockDim.x + threadIdx.x;
    if (i >= RQ_T + RK_T) return;
    if (i < RQ_T) {
        int d = i & 63;
        int rest = i >> 6;
        int hh = rest % NH;
        int t  = rest / NH;
        const float scale = 0.08838834764831843f;
        float2 cs = g_tab[t * 64 + d];
        size_t base = (size_t)t * (NH * DH) + (size_t)hh * DH;
        float x1 = q[base + d];
        float x2 = q[base + d + 64];
        float y1 = (x1 * cs.x - x2 * cs.y) * scale;
        float y2 = (x2 * cs.x + x1 * cs.y) * scale;
        __half h1 = __float2half_rn(y1);
        __half h2 = __float2half_rn(y2);
        g_qh[base + d]      = h1;
        g_ql[base + d]      = __float2half_rn(y1 - __half2float(h1));
        g_qh[base + d + 64] = h2;
        g_ql[base + d + 64] = __float2half_rn(y2 - __half2float(h2));
    } else {
        int j = i - RQ_T;
        int d = j & 63;
        int rest = j >> 6;
        int hh = rest % NKV;
        int t  = rest / NKV;
        float2 cs = g_tab[t * 64 + d];
        size_t base = (size_t)t * (NKV * DH) + (size_t)hh * DH;
        float x1 = k[base + d];
        float x2 = k[base + d + 64];
        float y1 = x1 * cs.x - x2 * cs.y;
        float y2 = x2 * cs.x + x1 * cs.y;
        k[base + d]      = y1;
        k[base + d + 64] = y2;
        g_ktr[((size_t)hh * DH + d) * TSEQ + t]      = __float2half_rn(y1);
        g_ktr[((size_t)hh * DH + d + 64) * TSEQ + t] = __float2half_rn(y2);
    }
}

// ---------------------------------------------------------------------------
// MMA flash attention: 128 q-rows/CTA, 256 threads. Q fp16 hi/lo (pre-scaled),
// K/V plain fp16 (K pre-transposed), P split x2. cp.async 2-stage KV.
// Grid (NH, T/128); m0 reversed for wave balance. (unchanged, proven)
// ---------------------------------------------------------------------------
#define A2_Q  34816u    // [128][272B]
#define A2_KT 18432u    // [128][144B]
#define A2_V  17408u    // [64][272B]
#define O_QH 0u
#define O_QL A2_Q
#define O_KV0 (2u * A2_Q)
#define KV_BUF (A2_KT + A2_V)
#define A2_SMEM (2u * A2_Q + 2u * KV_BUF)   // 141312

__global__ __launch_bounds__(256, 1) void attn_mma(
    __half* __restrict__ oh, __half* __restrict__ ol)
{
    extern __shared__ char sm[];
    const uint32_t sb = smem_u32(sm);
    const int h  = blockIdx.x;
    const int m0 = (int)(gridDim.y - 1 - blockIdx.y) << 7;
    const int kvh = h / GRP;
    const int tid = threadIdx.x;
    const int wid = tid >> 5;
    const int lane = tid & 31;
    const int wm = wid << 4;
    const int gID = lane >> 2;
    const int tig = lane & 3;

    const __half* ktr_h = g_ktr + (size_t)kvh * DH * TSEQ;

    auto issue_kv = [&](int n0, int b) {
        const uint32_t kb = sb + O_KV0 + (uint32_t)b * KV_BUF;
        #pragma unroll
        for (int i = 0; i < 4; i++) {
            int idx = tid + i * 256;
            int dr = idx >> 3, dc = idx & 7;
            cp16(kb + (uint32_t)(dr * 144 + dc * 16),
                 ktr_h + (size_t)dr * TSEQ + n0 + dc * 8);
            int vr = idx >> 4, vc = idx & 15;
            cp16(kb + A2_KT + (uint32_t)(vr * 272 + vc * 16),
                 g_v + (size_t)(n0 + vr) * (NKV * DH) + (size_t)kvh * DH + vc * 8);
        }
    };

    // load Q tile (128 x 128) hi/lo
    #pragma unroll
    for (int i = 0; i < 8; i++) {
        int idx = tid + i * 256;
        int r = idx >> 4, ch = idx & 15;
        const size_t go = (size_t)(m0 + r) * (NH * DH) + (size_t)h * DH + ch * 8;
        *(uint4*)(sm + O_QH + r * 272 + ch * 16) = *(const uint4*)(g_qh + go);
        *(uint4*)(sm + O_QL + r * 272 + ch * 16) = *(const uint4*)(g_ql + go);
    }

    float oacc[16][4];
    #pragma unroll
    for (int j = 0; j < 16; j++)
        #pragma unroll
        for (int q = 0; q < 4; q++) oacc[j][q] = 0.f;
    float m_run0 = -1e30f, m_run1 = -1e30f, l_run0 = 0.f, l_run1 = 0.f;

    const int row0 = m0 + wm + gID;
    const int row1 = row0 + 8;
    const int warp_max_row = m0 + wm + 15;

    const int nblocks = (m0 >> 6) + 2;
    issue_kv(0, 0); CP_COMMIT();

    for (int blk = 0; blk < nblocks; blk++) {
        const int n0 = blk << 6;
        const bool more = (blk + 1 < nblocks);
        if (more) { issue_kv((blk + 1) << 6, (blk + 1) & 1); CP_COMMIT(); CP_WAIT(1); }
        else      { CP_WAIT(0); }
        __syncthreads();

        if (n0 <= warp_max_row) {
            const uint32_t kb = sb + O_KV0 + (uint32_t)(blk & 1) * KV_BUF;

            // ---- S = Q K^T (2 products) ----
            float sacc[8][4];
            #pragma unroll
            for (int j = 0; j < 8; j++)
                #pragma unroll
                for (int q = 0; q < 4; q++) sacc[j][q] = 0.f;

            #pragma unroll
            for (int ks = 0; ks < 8; ks++) {
                uint32_t aH[4], aL[4];
                uint32_t ro = sb + O_QH + (uint32_t)((wm + (lane & 15)) * 272
                                                     + ks * 32 + (lane >> 4) * 16);
                ldsm4(aH, ro);
                ldsm4(aL, ro + A2_Q);
                const uint32_t kro = kb
                    + (uint32_t)((ks * 16 + (lane & 15)) * 144 + (lane >> 4) * 16);
                #pragma unroll
                for (int nb = 0; nb < 4; nb++) {
                    uint32_t bk4[4];
                    ldsm4t(bk4, kro + (uint32_t)(nb * 32));
                    #pragma unroll
                    for (int hh = 0; hh < 2; hh++) {
                        float (&cc)[4] = sacc[nb * 2 + hh];
                        mma_f16(cc, aH, bk4[2 * hh], bk4[2 * hh + 1]);
                        mma_f16(cc, aL, bk4[2 * hh], bk4[2 * hh + 1]);
                    }
                }
            }

            // ---- online softmax ----
            float mx0 = -1e30f, mx1 = -1e30f;
            #pragma unroll
            for (int nb = 0; nb < 8; nb++) {
                #pragma unroll
                for (int j = 0; j < 2; j++) {
                    const int col = n0 + nb * 8 + tig * 2 + j;
                    float s0 = sacc[nb][j];
                    float s1 = sacc[nb][2 + j];
                    if (col > row0) s0 = -1e30f;
                    if (col > row1) s1 = -1e30f;
                    sacc[nb][j] = s0;
                    sacc[nb][2 + j] = s1;
                    mx0 = fmaxf(mx0, s0);
                    mx1 = fmaxf(mx1, s1);
                }
            }
            #pragma unroll
            for (int off = 1; off <= 2; off <<= 1) {
                mx0 = fmaxf(mx0, __shfl_xor_sync(0xffffffffu, mx0, off));
                mx1 = fmaxf(mx1, __shfl_xor_sync(0xffffffffu, mx1, off));
            }
            float mn0 = fmaxf(m_run0, mx0);
            float mn1 = fmaxf(m_run1, mx1);
            float cf0 = __expf(m_run0 - mn0);
            float cf1 = __expf(m_run1 - mn1);
            m_run0 = mn0; m_run1 = mn1;
            float su0 = 0.f, su1 = 0.f;
            #pragma unroll
            for (int nb = 0; nb < 8; nb++) {
                #pragma unroll
                for (int j = 0; j < 2; j++) {
                    float p0 = __expf(sacc[nb][j] - mn0);
                    float p1 = __expf(sacc[nb][2 + j] - mn1);
                    sacc[nb][j] = p0;
                    sacc[nb][2 + j] = p1;
                    su0 += p0;
                    su1 += p1;
                }
            }
            #pragma unroll
            for (int off = 1; off <= 2; off <<= 1) {
                su0 += __shfl_xor_sync(0xffffffffu, su0, off);
                su1 += __shfl_xor_sync(0xffffffffu, su1, off);
            }
            l_run0 = l_run0 * cf0 + su0;
            l_run1 = l_run1 * cf1 + su1;
            #pragma unroll
            for (int j = 0; j < 16; j++) {
                oacc[j][0] *= cf0;
                oacc[j][1] *= cf0;
                oacc[j][2] *= cf1;
                oacc[j][3] *= cf1;
            }

            // ---- O += P V (2 products; P split register-direct) ----
            #pragma unroll
            for (int ks = 0; ks < 4; ks++) {
                uint32_t ph[4], pl[4];
                split_pack_f16(sacc[2 * ks][0],     sacc[2 * ks][1],     ph[0], pl[0]);
                split_pack_f16(sacc[2 * ks][2],     sacc[2 * ks][3],     ph[1], pl[1]);
                split_pack_f16(sacc[2 * ks + 1][0], sacc[2 * ks + 1][1], ph[2], pl[2]);
                split_pack_f16(sacc[2 * ks + 1][2], sacc[2 * ks + 1][3], ph[3], pl[3]);
                const uint32_t vro = kb + A2_KT
                    + (uint32_t)((ks * 16 + (lane & 15)) * 272 + (lane >> 4) * 16);
                #pragma unroll
                for (int nbv = 0; nbv < 8; nbv++) {
                    uint32_t vb4[4];
                    ldsm4t(vb4, vro + (uint32_t)(nbv * 32));
                    #pragma unroll
                    for (int hh = 0; hh < 2; hh++) {
                        float (&cc)[4] = oacc[nbv * 2 + hh];
                        mma_f16(cc, ph, vb4[2 * hh], vb4[2 * hh + 1]);
                        mma_f16(cc, pl, vb4[2 * hh], vb4[2 * hh + 1]);
                    }
                }
            }
        }
        __syncthreads();
    }

    // epilogue: write fp16 hi/lo split of normalized output
    const float inv0 = 1.0f / l_run0;
    const float inv1 = 1.0f / l_run1;
    #pragma unroll
    for (int onb = 0; onb < 16; onb++) {
        const int col = h * DH + onb * 8 + tig * 2;
        const size_t i0 = (size_t)row0 * (NH * DH) + col;
        const size_t i1 = (size_t)row1 * (NH * DH) + col;
        uint32_t hh_, ll_;
        split_pack_f16(oacc[onb][0] * inv0, oacc[onb][1] * inv0, hh_, ll_);
        *(uint32_t*)(oh + i0) = hh_;
        *(uint32_t*)(ol + i0) = ll_;
        split_pack_f16(oacc[onb][2] * inv1, oacc[onb][3] * inv1, hh_, ll_);
        *(uint32_t*)(oh + i1) = hh_;
        *(uint32_t*)(ol + i1) = ll_;
    }
}

// ---------------------------------------------------------------------------
extern "C" void kernel_launch(void* const* d_in, const int* in_sizes, int n_in,
                              void* d_out, int out_size)
{
    const int*   positions = (const int*)d_in[0];
    const float* hs = (const float*)d_in[1];
    const float* Wq = (const float*)d_in[2];
    const float* bq = (const float*)d_in[3];
    const float* Wk = (const float*)d_in[4];
    const float* bk = (const float*)d_in[5];
    const float* Wv = (const float*)d_in[6];
    const float* bv = (const float*)d_in[7];
    const float* Wo = (const float*)d_in[8];

    float* out  = (float*)d_out;
    float* kout = out + (size_t)TSEQ * HID;
    float* vout = kout + (size_t)TSEQ * NKV * DH;

    float *qbuf;
    __half *aah, *aal;
    cudaGetSymbolAddress((void**)&qbuf, g_q);
    cudaGetSymbolAddress((void**)&aah, g_ah);
    cudaGetSymbolAddress((void**)&aal, g_al);

    cudaFuncSetAttribute(tgemm_qkv, cudaFuncAttributeMaxDynamicSharedMemorySize, (int)TG_SMEM);
    cudaFuncSetAttribute(tgemm_o, cudaFuncAttributeMaxDynamicSharedMemorySize, (int)TG_SMEM);
    cudaFuncSetAttribute(attn_mma, cudaFuncAttributeMaxDynamicSharedMemorySize, (int)A2_SMEM);

    // 1. fused prep (hs split, weight converts, rope table)
    prep_kernel<<<(PREP_TOT + 255) / 256, 256>>>(
        positions, (const float4*)hs, (const float4*)Wq, (const float4*)Wk,
        (const float4*)Wv, (const float4*)Wo);

    // 2. fused QKV projection
    tgemm_qkv<<<dim3(48, 16), 256, TG_SMEM>>>(bq, bk, bv, qbuf, kout, vout);

    // 3. fused rope
    rope_kernel<<<(RQ_T + RK_T + 255) / 256, 256>>>(qbuf, kout);

    // 4. attention
    attn_mma<<<dim3(NH, TSEQ / 128), 256, A2_SMEM>>>(aah, aal);

    // 5. O projection
    tgemm_o<<<dim3(32, 16), 256, TG_SMEM>>>(out);
}

// round 14
// speedup vs baseline: 1.0951x; 1.0227x over previous
#include <cuda_runtime.h>
#include <cuda_fp16.h>
#include <math.h>
#include <stdint.h>

#define TSEQ 2048
#define HID  4096
#define NH   32
#define NKV  8
#define DH   128
#define GRP  (NH / NKV)

// ---------------------------------------------------------------------------
// Scratch (allocation-free rule: __device__ globals)
// ---------------------------------------------------------------------------
__device__ float2 g_tab[(size_t)TSEQ * 64];              // rope (cos,sin)
__device__ __half g_hsh[(size_t)TSEQ * HID], g_hsl[(size_t)TSEQ * HID];
__device__ __half g_wq[(size_t)HID * NH * DH];
__device__ __half g_wk[(size_t)HID * NKV * DH];
__device__ __half g_wv[(size_t)HID * NKV * DH];
__device__ __half g_wo[(size_t)NH * DH * HID];
__device__ __half g_qh[(size_t)TSEQ * NH * DH], g_ql[(size_t)TSEQ * NH * DH];
__device__ __half g_ktr[(size_t)NKV * DH * TSEQ];        // K transposed [h][d][t]
__device__ __half g_v[(size_t)TSEQ * NKV * DH];
__device__ __half g_ah[(size_t)TSEQ * NH * DH], g_al[(size_t)TSEQ * NH * DH];

// ---------------------------------------------------------------------------
// helpers
// ---------------------------------------------------------------------------
__device__ __forceinline__ uint32_t smem_u32(const void* p) {
    uint32_t a;
    asm("{ .reg .u64 t; cvta.to.shared.u64 t, %1; cvt.u32.u64 %0, t; }"
        : "=r"(a) : "l"(p));
    return a;
}
__device__ __forceinline__ uint32_t pack_f16x2(float x, float y) {
    __half2 h = __floats2half2_rn(x, y);
    return *(uint32_t*)&h;
}
__device__ __forceinline__ void split_pack_f16(float x, float y,
                                               uint32_t& hi, uint32_t& lo) {
    __half2 h = __floats2half2_rn(x, y);
    float2 b = __half22float2(h);
    __half2 l = __floats2half2_rn(x - b.x, y - b.y);
    hi = *(uint32_t*)&h;
    lo = *(uint32_t*)&l;
}
__device__ __forceinline__ void ldsm4(uint32_t (&r)[4], uint32_t a) {
    asm volatile("ldmatrix.sync.aligned.m8n8.x4.shared.b16 {%0,%1,%2,%3}, [%4];"
        : "=r"(r[0]), "=r"(r[1]), "=r"(r[2]), "=r"(r[3]) : "r"(a));
}
__device__ __forceinline__ void ldsm4t(uint32_t (&r)[4], uint32_t a) {
    asm volatile("ldmatrix.sync.aligned.m8n8.x4.trans.shared.b16 {%0,%1,%2,%3}, [%4];"
        : "=r"(r[0]), "=r"(r[1]), "=r"(r[2]), "=r"(r[3]) : "r"(a));
}
__device__ __forceinline__ void mma_f16(float (&c)[4], const uint32_t (&a)[4],
                                        uint32_t b0, uint32_t b1) {
    asm volatile("mma.sync.aligned.m16n8k16.row.col.f32.f16.f16.f32 "
        "{%0,%1,%2,%3}, {%4,%5,%6,%7}, {%8,%9}, {%0,%1,%2,%3};"
        : "+f"(c[0]), "+f"(c[1]), "+f"(c[2]), "+f"(c[3])
        : "r"(a[0]), "r"(a[1]), "r"(a[2]), "r"(a[3]), "r"(b0), "r"(b1));
}
__device__ __forceinline__ void cp16(uint32_t dst, const void* src) {
    asm volatile("cp.async.cg.shared.global [%0], [%1], 16;" :: "r"(dst), "l"(src));
}
#define CP_COMMIT() asm volatile("cp.async.commit_group;" ::: "memory")
#define CP_WAIT(n)  asm volatile("cp.async.wait_group %0;" :: "n"(n) : "memory")

// ---------------------------------------------------------------------------
// Fused prep: hs hi/lo split + all 4 weight converts + rope table.
// ---------------------------------------------------------------------------
#define HS_T  (TSEQ * HID / 8)
#define WQ_T  (HID * NH * DH / 8)
#define WK_T  (HID * NKV * DH / 8)
#define WV_T  (HID * NKV * DH / 8)
#define WO_T  (NH * DH * HID / 8)
#define TAB_T (TSEQ * 64)
#define PREP_TOT (HS_T + WQ_T + WK_T + WV_T + WO_T + TAB_T)

__global__ void prep_kernel(const int* __restrict__ positions,
                            const float4* __restrict__ hs,
                            const float4* __restrict__ wq,
                            const float4* __restrict__ wk,
                            const float4* __restrict__ wv,
                            const float4* __restrict__ wo)
{
    int i = blockIdx.x * blockDim.x + threadIdx.x;
    if (i >= PREP_TOT) return;
    int j = i;
    if (j < HS_T) {
        float4 v0 = hs[j * 2];
        float4 v1 = hs[j * 2 + 1];
        uint32_t h0, l0, h1, l1, h2, l2, h3, l3;
        split_pack_f16(v0.x, v0.y, h0, l0);
        split_pack_f16(v0.z, v0.w, h1, l1);
        split_pack_f16(v1.x, v1.y, h2, l2);
        split_pack_f16(v1.z, v1.w, h3, l3);
        ((uint4*)g_hsh)[j] = make_uint4(h0, h1, h2, h3);
        ((uint4*)g_hsl)[j] = make_uint4(l0, l1, l2, l3);
        return;
    }
    j -= HS_T;
    const float4* src;
    uint4* dst;
    if (j < WQ_T)                 { src = wq; dst = (uint4*)g_wq; }
    else if ((j -= WQ_T) < WK_T)  { src = wk; dst = (uint4*)g_wk; }
    else if ((j -= WK_T) < WV_T)  { src = wv; dst = (uint4*)g_wv; }
    else if ((j -= WV_T) < WO_T)  { src = wo; dst = (uint4*)g_wo; }
    else {
        j -= WO_T;                 // rope table entry
        int d = j & 63, t = j >> 6;
        float pos = (float)positions[t];
        float inv_freq = powf(1.0e6f, -(float)d * (1.0f / 64.0f));
        float s, c;
        sincosf(pos * inv_freq, &s, &c);
        g_tab[j] = make_float2(c, s);
        return;
    }
    float4 v0 = src[j * 2];
    float4 v1 = src[j * 2 + 1];
    dst[j] = make_uint4(pack_f16x2(v0.x, v0.y), pack_f16x2(v0.z, v0.w),
                        pack_f16x2(v1.x, v1.y), pack_f16x2(v1.z, v1.w));
}

// ---------------------------------------------------------------------------
// Core GEMM tile: C[bm:+128, bn:+128] = A@B (+bias). A fp16 hi/lo split,
// B plain fp16. K-chunk 64, 2-stage cp.async, one sync per chunk.
// 256 threads (4Mx2N warps), 2 CTAs/SM.
// mode 0: fp32 C. mode 1: fp32 C + fp16 copy (Ch). mode 2: rope -> g_qh/g_ql.
// mode 3: rope -> fp32 C (kout) + transposed fp16 g_ktr.
// ---------------------------------------------------------------------------
#define TG_AT 18432u            // A tile [128][144B]
#define TG_BT 17408u            // B tile [64][272B]
#define TG_BUF (2u * TG_AT + TG_BT)         // 54272
#define TG_SMEM (2u * TG_BUF)               // 108544  (>= stage 128*132*4)

__device__ __forceinline__ void gemm_tile(
    const __half* __restrict__ Ah, const __half* __restrict__ Al,
    const __half* __restrict__ B,
    const float* __restrict__ bias, float* __restrict__ C,
    __half* __restrict__ Ch,
    int N, int K, int bm, int bn, char* sm, int mode)
{
    const uint32_t sb = smem_u32(sm);
    const int tid  = threadIdx.x;
    const int wid  = tid >> 5;
    const int lane = tid & 31;
    const int wm = (wid >> 1) << 5;
    const int wn = (wid & 1) << 6;

    auto issue = [&](int k0, int buf) {
        const uint32_t base = sb + (uint32_t)buf * TG_BUF;
        #pragma unroll
        for (int i = 0; i < 4; i++) {
            int idx = tid + i * 256;
            int ar = idx >> 3, ac = idx & 7;
            const size_t aoff = (size_t)(bm + ar) * K + k0 + ac * 8;
            cp16(base + (uint32_t)(ar * 144 + ac * 16), Ah + aoff);
            cp16(base + TG_AT + (uint32_t)(ar * 144 + ac * 16), Al + aoff);
            int br = idx >> 4, bc = idx & 15;
            const size_t boff = (size_t)(k0 + br) * N + bn + bc * 8;
            cp16(base + 2u * TG_AT + (uint32_t)(br * 272 + bc * 16), B + boff);
        }
    };

    float acc[2][8][4];
    #pragma unroll
    for (int mi = 0; mi < 2; mi++)
        #pragma unroll
        for (int j = 0; j < 8; j++)
            #pragma unroll
            for (int q = 0; q < 4; q++) acc[mi][j][q] = 0.f;

    const int NC = K >> 6;
    issue(0, 0); CP_COMMIT();

    for (int c = 0; c < NC; c++) {
        CP_WAIT(0);
        __syncthreads();
        if (c + 1 < NC) { issue((c + 1) << 6, (c + 1) & 1); CP_COMMIT(); }

        const uint32_t base = sb + (uint32_t)(c & 1) * TG_BUF;
        #pragma unroll
        for (int ks = 0; ks < 4; ks++) {
            uint32_t afh[2][4], afl[2][4];
            #pragma unroll
            for (int mi = 0; mi < 2; mi++) {
                uint32_t ro = base + (uint32_t)((wm + mi * 16 + (lane & 15)) * 144
                                                + ks * 32 + (lane >> 4) * 16);
                ldsm4(afh[mi], ro);
                ldsm4(afl[mi], ro + TG_AT);
            }
            uint32_t bf[4][4];
            const uint32_t kro = base + 2u * TG_AT
                + (uint32_t)((ks * 16 + (lane & 15)) * 272 + (lane >> 4) * 16);
            #pragma unroll
            for (int nb = 0; nb < 4; nb++)
                ldsm4t(bf[nb], kro + (uint32_t)((wn + nb * 16) * 2));
            #pragma unroll
            for (int mi = 0; mi < 2; mi++)
                #pragma unroll
                for (int nb = 0; nb < 4; nb++)
                    #pragma unroll
                    for (int hh = 0; hh < 2; hh++) {
                        float (&cc)[4] = acc[mi][nb * 2 + hh];
                        mma_f16(cc, afh[mi], bf[nb][2 * hh], bf[nb][2 * hh + 1]);
                        mma_f16(cc, afl[mi], bf[nb][2 * hh], bf[nb][2 * hh + 1]);
                    }
        }
    }

    const int r0 = lane >> 2;
    const int c0 = (lane & 3) << 1;

    if (mode <= 1) {
        // plain epilogue
        #pragma unroll
        for (int mi = 0; mi < 2; mi++) {
            #pragma unroll
            for (int j = 0; j < 8; j++) {
                const int col = bn + wn + j * 8 + c0;
                float bias0 = 0.f, bias1 = 0.f;
                if (bias != nullptr) { bias0 = bias[col]; bias1 = bias[col + 1]; }
                const int row_a = bm + wm + mi * 16 + r0;
                const int row_b = row_a + 8;
                float va0 = acc[mi][j][0] + bias0, va1 = acc[mi][j][1] + bias1;
                float vb0 = acc[mi][j][2] + bias0, vb1 = acc[mi][j][3] + bias1;
                float* Ca = C + (size_t)row_a * N + col;
                float* Cb = C + (size_t)row_b * N + col;
                Ca[0] = va0; Ca[1] = va1;
                Cb[0] = vb0; Cb[1] = vb1;
                if (mode == 1) {
                    *(uint32_t*)(Ch + (size_t)row_a * N + col) = pack_f16x2(va0, va1);
                    *(uint32_t*)(Ch + (size_t)row_b * N + col) = pack_f16x2(vb0, vb1);
                }
            }
        }
        return;
    }

    // ---- rope modes: stage fp32 tile (+bias) to smem [128][132] ----
    float* S = (float*)sm;
    __syncthreads();   // all warps done reading mainloop smem
    #pragma unroll
    for (int mi = 0; mi < 2; mi++) {
        #pragma unroll
        for (int j = 0; j < 8; j++) {
            const int scol = wn + j * 8 + c0;
            float bias0 = 0.f, bias1 = 0.f;
            if (bias != nullptr) { bias0 = bias[bn + scol]; bias1 = bias[bn + scol + 1]; }
            const int sra = wm + mi * 16 + r0;
            S[sra * 132 + scol]           = acc[mi][j][0] + bias0;
            S[sra * 132 + scol + 1]       = acc[mi][j][1] + bias1;
            S[(sra + 8) * 132 + scol]     = acc[mi][j][2] + bias0;
            S[(sra + 8) * 132 + scol + 1] = acc[mi][j][3] + bias1;
        }
    }
    __syncthreads();

    const int head = bn >> 7;   // head index within this projection
    if (mode == 2) {
        // Q: rope + scale -> g_qh/g_ql  (d-fast; 2 d per iter for u32 stores)
        const float scale = 0.08838834764831843f;
        for (int i = tid; i < 128 * 32; i += 256) {
            int dp = i & 31, r = i >> 5;
            int d = dp * 2;
            int t = bm + r;
            float2 cs0 = g_tab[t * 64 + d];
            float2 cs1 = g_tab[t * 64 + d + 1];
            float x1a = S[r * 132 + d],      x1b = S[r * 132 + d + 1];
            float x2a = S[r * 132 + d + 64], x2b = S[r * 132 + d + 65];
            float y1a = (x1a * cs0.x - x2a * cs0.y) * scale;
            float y2a = (x2a * cs0.x + x1a * cs0.y) * scale;
            float y1b = (x1b * cs1.x - x2b * cs1.y) * scale;
            float y2b = (x2b * cs1.x + x1b * cs1.y) * scale;
            uint32_t h1_, l1_, h2_, l2_;
            split_pack_f16(y1a, y1b, h1_, l1_);
            split_pack_f16(y2a, y2b, h2_, l2_);
            const size_t go = (size_t)t * (NH * DH) + (size_t)head * DH + d;
            *(uint32_t*)(g_qh + go)      = h1_;
            *(uint32_t*)(g_ql + go)      = l1_;
            *(uint32_t*)(g_qh + go + 64) = h2_;
            *(uint32_t*)(g_ql + go + 64) = l2_;
        }
    } else {
        // K: pass A (d-fast) -> fp32 kout (kv_fused), coalesced float2 stores
        for (int i = tid; i < 128 * 32; i += 256) {
            int dp = i & 31, r = i >> 5;
            int d = dp * 2;
            int t = bm + r;
            float2 cs0 = g_tab[t * 64 + d];
            float2 cs1 = g_tab[t * 64 + d + 1];
            float x1a = S[r * 132 + d],      x1b = S[r * 132 + d + 1];
            float x2a = S[r * 132 + d + 64], x2b = S[r * 132 + d + 65];
            float y1a = x1a * cs0.x - x2a * cs0.y;
            float y2a = x2a * cs0.x + x1a * cs0.y;
            float y1b = x1b * cs1.x - x2b * cs1.y;
            float y2b = x2b * cs1.x + x1b * cs1.y;
            float* Cp = C + (size_t)t * (NKV * DH) + (size_t)head * DH + d;
            *(float2*)Cp        = make_float2(y1a, y1b);
            *(float2*)(Cp + 64) = make_float2(y2a, y2b);
        }
        // pass B (r-fast) -> transposed fp16 g_ktr, coalesced in t
        for (int i = tid; i < 64 * 128; i += 256) {
            int r = i & 127, d = i >> 7;     // d in 0..63
            int t = bm + r;
            float2 cs = g_tab[t * 64 + d];
            float x1 = S[r * 132 + d];
            float x2 = S[r * 132 + d + 64];
            float y1 = x1 * cs.x - x2 * cs.y;
            float y2 = x2 * cs.x + x1 * cs.y;
            g_ktr[((size_t)head * DH + d) * TSEQ + t]      = __float2half_rn(y1);
            g_ktr[((size_t)head * DH + d + 64) * TSEQ + t] = __float2half_rn(y2);
        }
    }
}

// Fused QKV projection + rope: grid (48, 16).
// bx<32 -> Q (rope->split fp16), [32,40) -> K (rope->fp32 + ktr), [40,48) -> V.
__global__ __launch_bounds__(256, 2) void tgemm_qkv(
    const float* __restrict__ bq, const float* __restrict__ bk,
    const float* __restrict__ bv,
    float* __restrict__ kout, float* __restrict__ vout)
{
    extern __shared__ char sm[];
    const int bx = blockIdx.x;
    const int bm = blockIdx.y << 7;
    if (bx < 32) {
        gemm_tile(g_hsh, g_hsl, g_wq, bq, nullptr, nullptr,
                  NH * DH, HID, bm, bx << 7, sm, 2);
    } else if (bx < 40) {
        gemm_tile(g_hsh, g_hsl, g_wk, bk, kout, nullptr,
                  NKV * DH, HID, bm, (bx - 32) << 7, sm, 3);
    } else {
        gemm_tile(g_hsh, g_hsl, g_wv, bv, vout, g_v,
                  NKV * DH, HID, bm, (bx - 40) << 7, sm, 1);
    }
}

// O projection: grid (32, 16).
__global__ __launch_bounds__(256, 2) void tgemm_o(float* __restrict__ out)
{
    extern __shared__ char sm[];
    gemm_tile(g_ah, g_al, g_wo, nullptr, out, nullptr,
              HID, NH * DH, blockIdx.y << 7, blockIdx.x << 7, sm, 0);
}

// ---------------------------------------------------------------------------
// MMA flash attention: 128 q-rows/CTA, 256 threads. Q fp16 hi/lo (pre-scaled),
// K/V plain fp16 (K pre-transposed), P split x2. cp.async 2-stage KV.
// Grid (NH, T/128); m0 reversed for wave balance. (unchanged, proven)
// ---------------------------------------------------------------------------
#define A2_Q  34816u    // [128][272B]
#define A2_KT 18432u    // [128][144B]
#define A2_V  17408u    // [64][272B]
#define O_QH 0u
#define O_QL A2_Q
#define O_KV0 (2u * A2_Q)
#define KV_BUF (A2_KT + A2_V)
#define A2_SMEM (2u * A2_Q + 2u * KV_BUF)   // 141312

__global__ __launch_bounds__(256, 1) void attn_mma(
    __half* __restrict__ oh, __half* __restrict__ ol)
{
    extern __shared__ char sm[];
    const uint32_t sb = smem_u32(sm);
    const int h  = blockIdx.x;
    const int m0 = (int)(gridDim.y - 1 - blockIdx.y) << 7;
    const int kvh = h / GRP;
    const int tid = threadIdx.x;
    const int wid = tid >> 5;
    const int lane = tid & 31;
    const int wm = wid << 4;
    const int gID = lane >> 2;
    const int tig = lane & 3;

    const __half* ktr_h = g_ktr + (size_t)kvh * DH * TSEQ;

    auto issue_kv = [&](int n0, int b) {
        const uint32_t kb = sb + O_KV0 + (uint32_t)b * KV_BUF;
        #pragma unroll
        for (int i = 0; i < 4; i++) {
            int idx = tid + i * 256;
            int dr = idx >> 3, dc = idx & 7;
            cp16(kb + (uint32_t)(dr * 144 + dc * 16),
                 ktr_h + (size_t)dr * TSEQ + n0 + dc * 8);
            int vr = idx >> 4, vc = idx & 15;
            cp16(kb + A2_KT + (uint32_t)(vr * 272 + vc * 16),
                 g_v + (size_t)(n0 + vr) * (NKV * DH) + (size_t)kvh * DH + vc * 8);
        }
    };

    // load Q tile (128 x 128) hi/lo
    #pragma unroll
    for (int i = 0; i < 8; i++) {
        int idx = tid + i * 256;
        int r = idx >> 4, ch = idx & 15;
        const size_t go = (size_t)(m0 + r) * (NH * DH) + (size_t)h * DH + ch * 8;
        *(uint4*)(sm + O_QH + r * 272 + ch * 16) = *(const uint4*)(g_qh + go);
        *(uint4*)(sm + O_QL + r * 272 + ch * 16) = *(const uint4*)(g_ql + go);
    }

    float oacc[16][4];
    #pragma unroll
    for (int j = 0; j < 16; j++)
        #pragma unroll
        for (int q = 0; q < 4; q++) oacc[j][q] = 0.f;
    float m_run0 = -1e30f, m_run1 = -1e30f, l_run0 = 0.f, l_run1 = 0.f;

    const int row0 = m0 + wm + gID;
    const int row1 = row0 + 8;
    const int warp_max_row = m0 + wm + 15;

    const int nblocks = (m0 >> 6) + 2;
    issue_kv(0, 0); CP_COMMIT();

    for (int blk = 0; blk < nblocks; blk++) {
        const int n0 = blk << 6;
        const bool more = (blk + 1 < nblocks);
        if (more) { issue_kv((blk + 1) << 6, (blk + 1) & 1); CP_COMMIT(); CP_WAIT(1); }
        else      { CP_WAIT(0); }
        __syncthreads();

        if (n0 <= warp_max_row) {
            const uint32_t kb = sb + O_KV0 + (uint32_t)(blk & 1) * KV_BUF;

            // ---- S = Q K^T (2 products) ----
            float sacc[8][4];
            #pragma unroll
            for (int j = 0; j < 8; j++)
                #pragma unroll
                for (int q = 0; q < 4; q++) sacc[j][q] = 0.f;

            #pragma unroll
            for (int ks = 0; ks < 8; ks++) {
                uint32_t aH[4], aL[4];
                uint32_t ro = sb + O_QH + (uint32_t)((wm + (lane & 15)) * 272
                                                     + ks * 32 + (lane >> 4) * 16);
                ldsm4(aH, ro);
                ldsm4(aL, ro + A2_Q);
                const uint32_t kro = kb
                    + (uint32_t)((ks * 16 + (lane & 15)) * 144 + (lane >> 4) * 16);
                #pragma unroll
                for (int nb = 0; nb < 4; nb++) {
                    uint32_t bk4[4];
                    ldsm4t(bk4, kro + (uint32_t)(nb * 32));
                    #pragma unroll
                    for (int hh = 0; hh < 2; hh++) {
                        float (&cc)[4] = sacc[nb * 2 + hh];
                        mma_f16(cc, aH, bk4[2 * hh], bk4[2 * hh + 1]);
                        mma_f16(cc, aL, bk4[2 * hh], bk4[2 * hh + 1]);
                    }
                }
            }

            // ---- online softmax ----
            float mx0 = -1e30f, mx1 = -1e30f;
            #pragma unroll
            for (int nb = 0; nb < 8; nb++) {
                #pragma unroll
                for (int j = 0; j < 2; j++) {
                    const int col = n0 + nb * 8 + tig * 2 + j;
                    float s0 = sacc[nb][j];
                    float s1 = sacc[nb][2 + j];
                    if (col > row0) s0 = -1e30f;
                    if (col > row1) s1 = -1e30f;
                    sacc[nb][j] = s0;
                    sacc[nb][2 + j] = s1;
                    mx0 = fmaxf(mx0, s0);
                    mx1 = fmaxf(mx1, s1);
                }
            }
            #pragma unroll
            for (int off = 1; off <= 2; off <<= 1) {
                mx0 = fmaxf(mx0, __shfl_xor_sync(0xffffffffu, mx0, off));
                mx1 = fmaxf(mx1, __shfl_xor_sync(0xffffffffu, mx1, off));
            }
            float mn0 = fmaxf(m_run0, mx0);
            float mn1 = fmaxf(m_run1, mx1);
            float cf0 = __expf(m_run0 - mn0);
            float cf1 = __expf(m_run1 - mn1);
            m_run0 = mn0; m_run1 = mn1;
            float su0 = 0.f, su1 = 0.f;
            #pragma unroll
            for (int nb = 0; nb < 8; nb++) {
                #pragma unroll
                for (int j = 0; j < 2; j++) {
                    float p0 = __expf(sacc[nb][j] - mn0);
                    float p1 = __expf(sacc[nb][2 + j] - mn1);
                    sacc[nb][j] = p0;
                    sacc[nb][2 + j] = p1;
                    su0 += p0;
                    su1 += p1;
                }
            }
            #pragma unroll
            for (int off = 1; off <= 2; off <<= 1) {
                su0 += __shfl_xor_sync(0xffffffffu, su0, off);
                su1 += __shfl_xor_sync(0xffffffffu, su1, off);
            }
            l_run0 = l_run0 * cf0 + su0;
            l_run1 = l_run1 * cf1 + su1;
            #pragma unroll
            for (int j = 0; j < 16; j++) {
                oacc[j][0] *= cf0;
                oacc[j][1] *= cf0;
                oacc[j][2] *= cf1;
                oacc[j][3] *= cf1;
            }

            // ---- O += P V (2 products; P split register-direct) ----
            #pragma unroll
            for (int ks = 0; ks < 4; ks++) {
                uint32_t ph[4], pl[4];
                split_pack_f16(sacc[2 * ks][0],     sacc[2 * ks][1],     ph[0], pl[0]);
                split_pack_f16(sacc[2 * ks][2],     sacc[2 * ks][3],     ph[1], pl[1]);
                split_pack_f16(sacc[2 * ks + 1][0], sacc[2 * ks + 1][1], ph[2], pl[2]);
                split_pack_f16(sacc[2 * ks + 1][2], sacc[2 * ks + 1][3], ph[3], pl[3]);
                const uint32_t vro = kb + A2_KT
                    + (uint32_t)((ks * 16 + (lane & 15)) * 272 + (lane >> 4) * 16);
                #pragma unroll
                for (int nbv = 0; nbv < 8; nbv++) {
                    uint32_t vb4[4];
                    ldsm4t(vb4, vro + (uint32_t)(nbv * 32));
                    #pragma unroll
                    for (int hh = 0; hh < 2; hh++) {
                        float (&cc)[4] = oacc[nbv * 2 + hh];
                        mma_f16(cc, ph, vb4[2 * hh], vb4[2 * hh + 1]);
                        mma_f16(cc, pl, vb4[2 * hh], vb4[2 * hh + 1]);
                    }
                }
            }
        }
        __syncthreads();
    }

    // epilogue: write fp16 hi/lo split of normalized output
    const float inv0 = 1.0f / l_run0;
    const float inv1 = 1.0f / l_run1;
    #pragma unroll
    for (int onb = 0; onb < 16; onb++) {
        const int col = h * DH + onb * 8 + tig * 2;
        const size_t i0 = (size_t)row0 * (NH * DH) + col;
        const size_t i1 = (size_t)row1 * (NH * DH) + col;
        uint32_t hh_, ll_;
        split_pack_f16(oacc[onb][0] * inv0, oacc[onb][1] * inv0, hh_, ll_);
        *(uint32_t*)(oh + i0) = hh_;
        *(uint32_t*)(ol + i0) = ll_;
        split_pack_f16(oacc[onb][2] * inv1, oacc[onb][3] * inv1, hh_, ll_);
        *(uint32_t*)(oh + i1) = hh_;
        *(uint32_t*)(ol + i1) = ll_;
    }
}

// ---------------------------------------------------------------------------
extern "C" void kernel_launch(void* const* d_in, const int* in_sizes, int n_in,
                              void* d_out, int out_size)
{
    const int*   positions = (const int*)d_in[0];
    const float* hs = (const float*)d_in[1];
    const float* Wq = (const float*)d_in[2];
    const float* bq = (const float*)d_in[3];
    const float* Wk = (const float*)d_in[4];
    const float* bk = (const float*)d_in[5];
    const float* Wv = (const float*)d_in[6];
    const float* bv = (const float*)d_in[7];
    const float* Wo = (const float*)d_in[8];

    float* out  = (float*)d_out;
    float* kout = out + (size_t)TSEQ * HID;
    float* vout = kout + (size_t)TSEQ * NKV * DH;

    __half *aah, *aal;
    cudaGetSymbolAddress((void**)&aah, g_ah);
    cudaGetSymbolAddress((void**)&aal, g_al);

    cudaFuncSetAttribute(tgemm_qkv, cudaFuncAttributeMaxDynamicSharedMemorySize, (int)TG_SMEM);
    cudaFuncSetAttribute(tgemm_o, cudaFuncAttributeMaxDynamicSharedMemorySize, (int)TG_SMEM);
    cudaFuncSetAttribute(attn_mma, cudaFuncAttributeMaxDynamicSharedMemorySize, (int)A2_SMEM);

    // 1. fused prep (hs split, weight converts, rope table)
    prep_kernel<<<(PREP_TOT + 255) / 256, 256>>>(
        positions, (const float4*)hs, (const float4*)Wq, (const float4*)Wk,
        (const float4*)Wv, (const float4*)Wo);

    // 2. fused QKV projection + rope (rope kernel eliminated)
    tgemm_qkv<<<dim3(48, 16), 256, TG_SMEM>>>(bq, bk, bv, kout, vout);

    // 3. attention
    attn_mma<<<dim3(NH, TSEQ / 128), 256, A2_SMEM>>>(aah, aal);

    // 4. O projection
    tgemm_o<<<dim3(32, 16), 256, TG_SMEM>>>(out);
}

// round 15
// speedup vs baseline: 1.0996x; 1.0041x over previous
#include <cuda_runtime.h>
#include <cuda_fp16.h>
#include <math.h>
#include <stdint.h>

#define TSEQ 2048
#define HID  4096
#define NH   32
#define NKV  8
#define DH   128
#define GRP  (NH / NKV)

// ---------------------------------------------------------------------------
// Scratch (allocation-free rule: __device__ globals)
// ---------------------------------------------------------------------------
__device__ float2 g_tab[(size_t)TSEQ * 64];              // rope (cos,sin)
__device__ __half g_hsh[(size_t)TSEQ * HID], g_hsl[(size_t)TSEQ * HID];
__device__ __half g_wq[(size_t)HID * NH * DH];
__device__ __half g_wk[(size_t)HID * NKV * DH];
__device__ __half g_wv[(size_t)HID * NKV * DH];
__device__ __half g_wo[(size_t)NH * DH * HID];
__device__ __half g_qh[(size_t)TSEQ * NH * DH], g_ql[(size_t)TSEQ * NH * DH];
__device__ __half g_ktr[(size_t)NKV * DH * TSEQ];        // K transposed [h][d][t]
__device__ __half g_v[(size_t)TSEQ * NKV * DH];
__device__ __half g_ah[(size_t)TSEQ * NH * DH], g_al[(size_t)TSEQ * NH * DH];

// ---------------------------------------------------------------------------
// helpers
// ---------------------------------------------------------------------------
__device__ __forceinline__ uint32_t smem_u32(const void* p) {
    uint32_t a;
    asm("{ .reg .u64 t; cvta.to.shared.u64 t, %1; cvt.u32.u64 %0, t; }"
        : "=r"(a) : "l"(p));
    return a;
}
__device__ __forceinline__ uint32_t pack_f16x2(float x, float y) {
    __half2 h = __floats2half2_rn(x, y);
    return *(uint32_t*)&h;
}
__device__ __forceinline__ void split_pack_f16(float x, float y,
                                               uint32_t& hi, uint32_t& lo) {
    __half2 h = __floats2half2_rn(x, y);
    float2 b = __half22float2(h);
    __half2 l = __floats2half2_rn(x - b.x, y - b.y);
    hi = *(uint32_t*)&h;
    lo = *(uint32_t*)&l;
}
__device__ __forceinline__ void ldsm4(uint32_t (&r)[4], uint32_t a) {
    asm volatile("ldmatrix.sync.aligned.m8n8.x4.shared.b16 {%0,%1,%2,%3}, [%4];"
        : "=r"(r[0]), "=r"(r[1]), "=r"(r[2]), "=r"(r[3]) : "r"(a));
}
__device__ __forceinline__ void ldsm4t(uint32_t (&r)[4], uint32_t a) {
    asm volatile("ldmatrix.sync.aligned.m8n8.x4.trans.shared.b16 {%0,%1,%2,%3}, [%4];"
        : "=r"(r[0]), "=r"(r[1]), "=r"(r[2]), "=r"(r[3]) : "r"(a));
}
__device__ __forceinline__ void mma_f16(float (&c)[4], const uint32_t (&a)[4],
                                        uint32_t b0, uint32_t b1) {
    asm volatile("mma.sync.aligned.m16n8k16.row.col.f32.f16.f16.f32 "
        "{%0,%1,%2,%3}, {%4,%5,%6,%7}, {%8,%9}, {%0,%1,%2,%3};"
        : "+f"(c[0]), "+f"(c[1]), "+f"(c[2]), "+f"(c[3])
        : "r"(a[0]), "r"(a[1]), "r"(a[2]), "r"(a[3]), "r"(b0), "r"(b1));
}
__device__ __forceinline__ void cp16(uint32_t dst, const void* src) {
    asm volatile("cp.async.cg.shared.global [%0], [%1], 16;" :: "r"(dst), "l"(src));
}
#define CP_COMMIT() asm volatile("cp.async.commit_group;" ::: "memory")
#define CP_WAIT(n)  asm volatile("cp.async.wait_group %0;" :: "n"(n) : "memory")

// ---------------------------------------------------------------------------
// Fused prep: hs hi/lo split + all 4 weight converts + rope table.
// 16 elems/thread on the convert paths for higher MLP.
// ---------------------------------------------------------------------------
#define HS_G  (TSEQ * HID / 16)
#define WQ_G  (HID * NH * DH / 16)
#define WK_G  (HID * NKV * DH / 16)
#define WV_G  (HID * NKV * DH / 16)
#define WO_G  (NH * DH * HID / 16)
#define TAB_T (TSEQ * 64)
#define PREP_TOT (HS_G + WQ_G + WK_G + WV_G + WO_G + TAB_T)

__global__ void prep_kernel(const int* __restrict__ positions,
                            const float4* __restrict__ hs,
                            const float4* __restrict__ wq,
                            const float4* __restrict__ wk,
                            const float4* __restrict__ wv,
                            const float4* __restrict__ wo)
{
    int i = blockIdx.x * blockDim.x + threadIdx.x;
    if (i >= PREP_TOT) return;
    int j = i;
    if (j < HS_G) {
        // 16 elems: 4x float4 in flight
        float4 v[4];
        #pragma unroll
        for (int q = 0; q < 4; q++) v[q] = hs[j * 4 + q];
        #pragma unroll
        for (int q = 0; q < 2; q++) {
            uint32_t h0, l0, h1, l1, h2, l2, h3, l3;
            split_pack_f16(v[2*q].x, v[2*q].y, h0, l0);
            split_pack_f16(v[2*q].z, v[2*q].w, h1, l1);
            split_pack_f16(v[2*q+1].x, v[2*q+1].y, h2, l2);
            split_pack_f16(v[2*q+1].z, v[2*q+1].w, h3, l3);
            ((uint4*)g_hsh)[j * 2 + q] = make_uint4(h0, h1, h2, h3);
            ((uint4*)g_hsl)[j * 2 + q] = make_uint4(l0, l1, l2, l3);
        }
        return;
    }
    j -= HS_G;
    const float4* src;
    uint4* dst;
    if (j < WQ_G)                 { src = wq; dst = (uint4*)g_wq; }
    else if ((j -= WQ_G) < WK_G)  { src = wk; dst = (uint4*)g_wk; }
    else if ((j -= WK_G) < WV_G)  { src = wv; dst = (uint4*)g_wv; }
    else if ((j -= WV_G) < WO_G)  { src = wo; dst = (uint4*)g_wo; }
    else {
        j -= WO_G;                 // rope table entry
        int d = j & 63, t = j >> 6;
        float pos = (float)positions[t];
        float inv_freq = powf(1.0e6f, -(float)d * (1.0f / 64.0f));
        float s, c;
        sincosf(pos * inv_freq, &s, &c);
        g_tab[j] = make_float2(c, s);
        return;
    }
    float4 v[4];
    #pragma unroll
    for (int q = 0; q < 4; q++) v[q] = src[j * 4 + q];
    #pragma unroll
    for (int q = 0; q < 2; q++)
        dst[j * 2 + q] = make_uint4(
            pack_f16x2(v[2*q].x, v[2*q].y),     pack_f16x2(v[2*q].z, v[2*q].w),
            pack_f16x2(v[2*q+1].x, v[2*q+1].y), pack_f16x2(v[2*q+1].z, v[2*q+1].w));
}

// ---------------------------------------------------------------------------
// Core GEMM tile (unchanged config; R13-proven). Modes as R14.
// ---------------------------------------------------------------------------
#define TG_AT 18432u            // A tile [128][144B]
#define TG_BT 17408u            // B tile [64][272B]
#define TG_BUF (2u * TG_AT + TG_BT)         // 54272
#define TG_SMEM (2u * TG_BUF)               // 108544  (>= stage 128*132*4)

__device__ __forceinline__ void gemm_tile(
    const __half* __restrict__ Ah, const __half* __restrict__ Al,
    const __half* __restrict__ B,
    const float* __restrict__ bias, float* __restrict__ C,
    __half* __restrict__ Ch,
    int N, int K, int bm, int bn, char* sm, int mode)
{
    const uint32_t sb = smem_u32(sm);
    const int tid  = threadIdx.x;
    const int wid  = tid >> 5;
    const int lane = tid & 31;
    const int wm = (wid >> 1) << 5;
    const int wn = (wid & 1) << 6;

    auto issue = [&](int k0, int buf) {
        const uint32_t base = sb + (uint32_t)buf * TG_BUF;
        #pragma unroll
        for (int i = 0; i < 4; i++) {
            int idx = tid + i * 256;
            int ar = idx >> 3, ac = idx & 7;
            const size_t aoff = (size_t)(bm + ar) * K + k0 + ac * 8;
            cp16(base + (uint32_t)(ar * 144 + ac * 16), Ah + aoff);
            cp16(base + TG_AT + (uint32_t)(ar * 144 + ac * 16), Al + aoff);
            int br = idx >> 4, bc = idx & 15;
            const size_t boff = (size_t)(k0 + br) * N + bn + bc * 8;
            cp16(base + 2u * TG_AT + (uint32_t)(br * 272 + bc * 16), B + boff);
        }
    };

    float acc[2][8][4];
    #pragma unroll
    for (int mi = 0; mi < 2; mi++)
        #pragma unroll
        for (int j = 0; j < 8; j++)
            #pragma unroll
            for (int q = 0; q < 4; q++) acc[mi][j][q] = 0.f;

    const int NC = K >> 6;
    issue(0, 0); CP_COMMIT();

    for (int c = 0; c < NC; c++) {
        CP_WAIT(0);
        __syncthreads();
        if (c + 1 < NC) { issue((c + 1) << 6, (c + 1) & 1); CP_COMMIT(); }

        const uint32_t base = sb + (uint32_t)(c & 1) * TG_BUF;
        #pragma unroll
        for (int ks = 0; ks < 4; ks++) {
            uint32_t afh[2][4], afl[2][4];
            #pragma unroll
            for (int mi = 0; mi < 2; mi++) {
                uint32_t ro = base + (uint32_t)((wm + mi * 16 + (lane & 15)) * 144
                                                + ks * 32 + (lane >> 4) * 16);
                ldsm4(afh[mi], ro);
                ldsm4(afl[mi], ro + TG_AT);
            }
            uint32_t bf[4][4];
            const uint32_t kro = base + 2u * TG_AT
                + (uint32_t)((ks * 16 + (lane & 15)) * 272 + (lane >> 4) * 16);
            #pragma unroll
            for (int nb = 0; nb < 4; nb++)
                ldsm4t(bf[nb], kro + (uint32_t)((wn + nb * 16) * 2));
            #pragma unroll
            for (int mi = 0; mi < 2; mi++)
                #pragma unroll
                for (int nb = 0; nb < 4; nb++)
                    #pragma unroll
                    for (int hh = 0; hh < 2; hh++) {
                        float (&cc)[4] = acc[mi][nb * 2 + hh];
                        mma_f16(cc, afh[mi], bf[nb][2 * hh], bf[nb][2 * hh + 1]);
                        mma_f16(cc, afl[mi], bf[nb][2 * hh], bf[nb][2 * hh + 1]);
                    }
        }
    }

    const int r0 = lane >> 2;
    const int c0 = (lane & 3) << 1;

    if (mode <= 1) {
        #pragma unroll
        for (int mi = 0; mi < 2; mi++) {
            #pragma unroll
            for (int j = 0; j < 8; j++) {
                const int col = bn + wn + j * 8 + c0;
                float bias0 = 0.f, bias1 = 0.f;
                if (bias != nullptr) { bias0 = bias[col]; bias1 = bias[col + 1]; }
                const int row_a = bm + wm + mi * 16 + r0;
                const int row_b = row_a + 8;
                float va0 = acc[mi][j][0] + bias0, va1 = acc[mi][j][1] + bias1;
                float vb0 = acc[mi][j][2] + bias0, vb1 = acc[mi][j][3] + bias1;
                float* Ca = C + (size_t)row_a * N + col;
                float* Cb = C + (size_t)row_b * N + col;
                Ca[0] = va0; Ca[1] = va1;
                Cb[0] = vb0; Cb[1] = vb1;
                if (mode == 1) {
                    *(uint32_t*)(Ch + (size_t)row_a * N + col) = pack_f16x2(va0, va1);
                    *(uint32_t*)(Ch + (size_t)row_b * N + col) = pack_f16x2(vb0, vb1);
                }
            }
        }
        return;
    }

    // ---- rope modes: stage fp32 tile (+bias) to smem [128][132] ----
    float* S = (float*)sm;
    __syncthreads();
    #pragma unroll
    for (int mi = 0; mi < 2; mi++) {
        #pragma unroll
        for (int j = 0; j < 8; j++) {
            const int scol = wn + j * 8 + c0;
            float bias0 = 0.f, bias1 = 0.f;
            if (bias != nullptr) { bias0 = bias[bn + scol]; bias1 = bias[bn + scol + 1]; }
            const int sra = wm + mi * 16 + r0;
            S[sra * 132 + scol]           = acc[mi][j][0] + bias0;
            S[sra * 132 + scol + 1]       = acc[mi][j][1] + bias1;
            S[(sra + 8) * 132 + scol]     = acc[mi][j][2] + bias0;
            S[(sra + 8) * 132 + scol + 1] = acc[mi][j][3] + bias1;
        }
    }
    __syncthreads();

    const int head = bn >> 7;
    if (mode == 2) {
        const float scale = 0.08838834764831843f;
        for (int i = tid; i < 128 * 32; i += 256) {
            int dp = i & 31, r = i >> 5;
            int d = dp * 2;
            int t = bm + r;
            float2 cs0 = g_tab[t * 64 + d];
            float2 cs1 = g_tab[t * 64 + d + 1];
            float x1a = S[r * 132 + d],      x1b = S[r * 132 + d + 1];
            float x2a = S[r * 132 + d + 64], x2b = S[r * 132 + d + 65];
            float y1a = (x1a * cs0.x - x2a * cs0.y) * scale;
            float y2a = (x2a * cs0.x + x1a * cs0.y) * scale;
            float y1b = (x1b * cs1.x - x2b * cs1.y) * scale;
            float y2b = (x2b * cs1.x + x1b * cs1.y) * scale;
            uint32_t h1_, l1_, h2_, l2_;
            split_pack_f16(y1a, y1b, h1_, l1_);
            split_pack_f16(y2a, y2b, h2_, l2_);
            const size_t go = (size_t)t * (NH * DH) + (size_t)head * DH + d;
            *(uint32_t*)(g_qh + go)      = h1_;
            *(uint32_t*)(g_ql + go)      = l1_;
            *(uint32_t*)(g_qh + go + 64) = h2_;
            *(uint32_t*)(g_ql + go + 64) = l2_;
        }
    } else {
        for (int i = tid; i < 128 * 32; i += 256) {
            int dp = i & 31, r = i >> 5;
            int d = dp * 2;
            int t = bm + r;
            float2 cs0 = g_tab[t * 64 + d];
            float2 cs1 = g_tab[t * 64 + d + 1];
            float x1a = S[r * 132 + d],      x1b = S[r * 132 + d + 1];
            float x2a = S[r * 132 + d + 64], x2b = S[r * 132 + d + 65];
            float y1a = x1a * cs0.x - x2a * cs0.y;
            float y2a = x2a * cs0.x + x1a * cs0.y;
            float y1b = x1b * cs1.x - x2b * cs1.y;
            float y2b = x2b * cs1.x + x1b * cs1.y;
            float* Cp = C + (size_t)t * (NKV * DH) + (size_t)head * DH + d;
            *(float2*)Cp        = make_float2(y1a, y1b);
            *(float2*)(Cp + 64) = make_float2(y2a, y2b);
        }
        for (int i = tid; i < 64 * 128; i += 256) {
            int r = i & 127, d = i >> 7;
            int t = bm + r;
            float2 cs = g_tab[t * 64 + d];
            float x1 = S[r * 132 + d];
            float x2 = S[r * 132 + d + 64];
            float y1 = x1 * cs.x - x2 * cs.y;
            float y2 = x2 * cs.x + x1 * cs.y;
            g_ktr[((size_t)head * DH + d) * TSEQ + t]      = __float2half_rn(y1);
            g_ktr[((size_t)head * DH + d + 64) * TSEQ + t] = __float2half_rn(y2);
        }
    }
}

// Fused QKV projection + rope: grid (16, 48): x = M-tile (fast) so that each
// scheduling wave reuses a narrow band of weight columns from L2.
// by<32 -> Q (rope->split fp16), [32,40) -> K (rope->fp32 + ktr), [40,48) -> V.
__global__ __launch_bounds__(256, 2) void tgemm_qkv(
    const float* __restrict__ bq, const float* __restrict__ bk,
    const float* __restrict__ bv,
    float* __restrict__ kout, float* __restrict__ vout)
{
    extern __shared__ char sm[];
    const int by = blockIdx.y;
    const int bm = (int)blockIdx.x << 7;
    if (by < 32) {
        gemm_tile(g_hsh, g_hsl, g_wq, bq, nullptr, nullptr,
                  NH * DH, HID, bm, by << 7, sm, 2);
    } else if (by < 40) {
        gemm_tile(g_hsh, g_hsl, g_wk, bk, kout, nullptr,
                  NKV * DH, HID, bm, (by - 32) << 7, sm, 3);
    } else {
        gemm_tile(g_hsh, g_hsl, g_wv, bv, vout, g_v,
                  NKV * DH, HID, bm, (by - 40) << 7, sm, 1);
    }
}

// O projection: grid (16, 32): x = M-tile (fast) for weight L2 reuse.
__global__ __launch_bounds__(256, 2) void tgemm_o(float* __restrict__ out)
{
    extern __shared__ char sm[];
    gemm_tile(g_ah, g_al, g_wo, nullptr, out, nullptr,
              HID, NH * DH, (int)blockIdx.x << 7, (int)blockIdx.y << 7, sm, 0);
}

// ---------------------------------------------------------------------------
// MMA flash attention (unchanged, proven).
// ---------------------------------------------------------------------------
#define A2_Q  34816u    // [128][272B]
#define A2_KT 18432u    // [128][144B]
#define A2_V  17408u    // [64][272B]
#define O_QH 0u
#define O_QL A2_Q
#define O_KV0 (2u * A2_Q)
#define KV_BUF (A2_KT + A2_V)
#define A2_SMEM (2u * A2_Q + 2u * KV_BUF)   // 141312

__global__ __launch_bounds__(256, 1) void attn_mma(
    __half* __restrict__ oh, __half* __restrict__ ol)
{
    extern __shared__ char sm[];
    const uint32_t sb = smem_u32(sm);
    const int h  = blockIdx.x;
    const int m0 = (int)(gridDim.y - 1 - blockIdx.y) << 7;
    const int kvh = h / GRP;
    const int tid = threadIdx.x;
    const int wid = tid >> 5;
    const int lane = tid & 31;
    const int wm = wid << 4;
    const int gID = lane >> 2;
    const int tig = lane & 3;

    const __half* ktr_h = g_ktr + (size_t)kvh * DH * TSEQ;

    auto issue_kv = [&](int n0, int b) {
        const uint32_t kb = sb + O_KV0 + (uint32_t)b * KV_BUF;
        #pragma unroll
        for (int i = 0; i < 4; i++) {
            int idx = tid + i * 256;
            int dr = idx >> 3, dc = idx & 7;
            cp16(kb + (uint32_t)(dr * 144 + dc * 16),
                 ktr_h + (size_t)dr * TSEQ + n0 + dc * 8);
            int vr = idx >> 4, vc = idx & 15;
            cp16(kb + A2_KT + (uint32_t)(vr * 272 + vc * 16),
                 g_v + (size_t)(n0 + vr) * (NKV * DH) + (size_t)kvh * DH + vc * 8);
        }
    };

    #pragma unroll
    for (int i = 0; i < 8; i++) {
        int idx = tid + i * 256;
        int r = idx >> 4, ch = idx & 15;
        const size_t go = (size_t)(m0 + r) * (NH * DH) + (size_t)h * DH + ch * 8;
        *(uint4*)(sm + O_QH + r * 272 + ch * 16) = *(const uint4*)(g_qh + go);
        *(uint4*)(sm + O_QL + r * 272 + ch * 16) = *(const uint4*)(g_ql + go);
    }

    float oacc[16][4];
    #pragma unroll
    for (int j = 0; j < 16; j++)
        #pragma unroll
        for (int q = 0; q < 4; q++) oacc[j][q] = 0.f;
    float m_run0 = -1e30f, m_run1 = -1e30f, l_run0 = 0.f, l_run1 = 0.f;

    const int row0 = m0 + wm + gID;
    const int row1 = row0 + 8;
    const int warp_max_row = m0 + wm + 15;

    const int nblocks = (m0 >> 6) + 2;
    issue_kv(0, 0); CP_COMMIT();

    for (int blk = 0; blk < nblocks; blk++) {
        const int n0 = blk << 6;
        const bool more = (blk + 1 < nblocks);
        if (more) { issue_kv((blk + 1) << 6, (blk + 1) & 1); CP_COMMIT(); CP_WAIT(1); }
        else      { CP_WAIT(0); }
        __syncthreads();

        if (n0 <= warp_max_row) {
            const uint32_t kb = sb + O_KV0 + (uint32_t)(blk & 1) * KV_BUF;

            float sacc[8][4];
            #pragma unroll
            for (int j = 0; j < 8; j++)
                #pragma unroll
                for (int q = 0; q < 4; q++) sacc[j][q] = 0.f;

            #pragma unroll
            for (int ks = 0; ks < 8; ks++) {
                uint32_t aH[4], aL[4];
                uint32_t ro = sb + O_QH + (uint32_t)((wm + (lane & 15)) * 272
                                                     + ks * 32 + (lane >> 4) * 16);
                ldsm4(aH, ro);
                ldsm4(aL, ro + A2_Q);
                const uint32_t kro = kb
                    + (uint32_t)((ks * 16 + (lane & 15)) * 144 + (lane >> 4) * 16);
                #pragma unroll
                for (int nb = 0; nb < 4; nb++) {
                    uint32_t bk4[4];
                    ldsm4t(bk4, kro + (uint32_t)(nb * 32));
                    #pragma unroll
                    for (int hh = 0; hh < 2; hh++) {
                        float (&cc)[4] = sacc[nb * 2 + hh];
                        mma_f16(cc, aH, bk4[2 * hh], bk4[2 * hh + 1]);
                        mma_f16(cc, aL, bk4[2 * hh], bk4[2 * hh + 1]);
                    }
                }
            }

            float mx0 = -1e30f, mx1 = -1e30f;
            #pragma unroll
            for (int nb = 0; nb < 8; nb++) {
                #pragma unroll
                for (int j = 0; j < 2; j++) {
                    const int col = n0 + nb * 8 + tig * 2 + j;
                    float s0 = sacc[nb][j];
                    float s1 = sacc[nb][2 + j];
                    if (col > row0) s0 = -1e30f;
                    if (col > row1) s1 = -1e30f;
                    sacc[nb][j] = s0;
                    sacc[nb][2 + j] = s1;
                    mx0 = fmaxf(mx0, s0);
                    mx1 = fmaxf(mx1, s1);
                }
            }
            #pragma unroll
            for (int off = 1; off <= 2; off <<= 1) {
                mx0 = fmaxf(mx0, __shfl_xor_sync(0xffffffffu, mx0, off));
                mx1 = fmaxf(mx1, __shfl_xor_sync(0xffffffffu, mx1, off));
            }
            float mn0 = fmaxf(m_run0, mx0);
            float mn1 = fmaxf(m_run1, mx1);
            float cf0 = __expf(m_run0 - mn0);
            float cf1 = __expf(m_run1 - mn1);
            m_run0 = mn0; m_run1 = mn1;
            float su0 = 0.f, su1 = 0.f;
            #pragma unroll
            for (int nb = 0; nb < 8; nb++) {
                #pragma unroll
                for (int j = 0; j < 2; j++) {
                    float p0 = __expf(sacc[nb][j] - mn0);
                    float p1 = __expf(sacc[nb][2 + j] - mn1);
                    sacc[nb][j] = p0;
                    sacc[nb][2 + j] = p1;
                    su0 += p0;
                    su1 += p1;
                }
            }
            #pragma unroll
            for (int off = 1; off <= 2; off <<= 1) {
                su0 += __shfl_xor_sync(0xffffffffu, su0, off);
                su1 += __shfl_xor_sync(0xffffffffu, su1, off);
            }
            l_run0 = l_run0 * cf0 + su0;
            l_run1 = l_run1 * cf1 + su1;
            #pragma unroll
            for (int j = 0; j < 16; j++) {
                oacc[j][0] *= cf0;
                oacc[j][1] *= cf0;
                oacc[j][2] *= cf1;
                oacc[j][3] *= cf1;
            }

            #pragma unroll
            for (int ks = 0; ks < 4; ks++) {
                uint32_t ph[4], pl[4];
                split_pack_f16(sacc[2 * ks][0],     sacc[2 * ks][1],     ph[0], pl[0]);
                split_pack_f16(sacc[2 * ks][2],     sacc[2 * ks][3],     ph[1], pl[1]);
                split_pack_f16(sacc[2 * ks + 1][0], sacc[2 * ks + 1][1], ph[2], pl[2]);
                split_pack_f16(sacc[2 * ks + 1][2], sacc[2 * ks + 1][3], ph[3], pl[3]);
                const uint32_t vro = kb + A2_KT
                    + (uint32_t)((ks * 16 + (lane & 15)) * 272 + (lane >> 4) * 16);
                #pragma unroll
                for (int nbv = 0; nbv < 8; nbv++) {
                    uint32_t vb4[4];
                    ldsm4t(vb4, vro + (uint32_t)(nbv * 32));
                    #pragma unroll
                    for (int hh = 0; hh < 2; hh++) {
                        float (&cc)[4] = oacc[nbv * 2 + hh];
                        mma_f16(cc, ph, vb4[2 * hh], vb4[2 * hh + 1]);
                        mma_f16(cc, pl, vb4[2 * hh], vb4[2 * hh + 1]);
                    }
                }
            }
        }
        __syncthreads();
    }

    const float inv0 = 1.0f / l_run0;
    const float inv1 = 1.0f / l_run1;
    #pragma unroll
    for (int onb = 0; onb < 16; onb++) {
        const int col = h * DH + onb * 8 + tig * 2;
        const size_t i0 = (size_t)row0 * (NH * DH) + col;
        const size_t i1 = (size_t)row1 * (NH * DH) + col;
        uint32_t hh_, ll_;
        split_pack_f16(oacc[onb][0] * inv0, oacc[onb][1] * inv0, hh_, ll_);
        *(uint32_t*)(oh + i0) = hh_;
        *(uint32_t*)(ol + i0) = ll_;
        split_pack_f16(oacc[onb][2] * inv1, oacc[onb][3] * inv1, hh_, ll_);
        *(uint32_t*)(oh + i1) = hh_;
        *(uint32_t*)(ol + i1) = ll_;
    }
}

// ---------------------------------------------------------------------------
extern "C" void kernel_launch(void* const* d_in, const int* in_sizes, int n_in,
                              void* d_out, int out_size)
{
    const int*   positions = (const int*)d_in[0];
    const float* hs = (const float*)d_in[1];
    const float* Wq = (const float*)d_in[2];
    const float* bq = (const float*)d_in[3];
    const float* Wk = (const float*)d_in[4];
    const float* bk = (const float*)d_in[5];
    const float* Wv = (const float*)d_in[6];
    const float* bv = (const float*)d_in[7];
    const float* Wo = (const float*)d_in[8];

    float* out  = (float*)d_out;
    float* kout = out + (size_t)TSEQ * HID;
    float* vout = kout + (size_t)TSEQ * NKV * DH;

    __half *aah, *aal;
    cudaGetSymbolAddress((void**)&aah, g_ah);
    cudaGetSymbolAddress((void**)&aal, g_al);

    cudaFuncSetAttribute(tgemm_qkv, cudaFuncAttributeMaxDynamicSharedMemorySize, (int)TG_SMEM);
    cudaFuncSetAttribute(tgemm_o, cudaFuncAttributeMaxDynamicSharedMemorySize, (int)TG_SMEM);
    cudaFuncSetAttribute(attn_mma, cudaFuncAttributeMaxDynamicSharedMemorySize, (int)A2_SMEM);

    // 1. fused prep (hs split, weight converts, rope table)
    prep_kernel<<<(PREP_TOT + 255) / 256, 256>>>(
        positions, (const float4*)hs, (const float4*)Wq, (const float4*)Wk,
        (const float4*)Wv, (const float4*)Wo);

    // 2. fused QKV projection + rope (M-tile-fast grid for L2 weight reuse)
    tgemm_qkv<<<dim3(16, 48), 256, TG_SMEM>>>(bq, bk, bv, kout, vout);

    // 3. attention
    attn_mma<<<dim3(NH, TSEQ / 128), 256, A2_SMEM>>>(aah, aal);

    // 4. O projection
    tgemm_o<<<dim3(16, 32), 256, TG_SMEM>>>(out);
}

// round 16
// speedup vs baseline: 1.1252x; 1.0233x over previous
#include <cuda_runtime.h>
#include <cuda_fp16.h>
#include <math.h>
#include <stdint.h>

#define TSEQ 2048
#define HID  4096
#define NH   32
#define NKV  8
#define DH   128
#define GRP  (NH / NKV)

// ---------------------------------------------------------------------------
// Scratch (allocation-free rule: __device__ globals)
// ---------------------------------------------------------------------------
__device__ float2 g_tab[(size_t)TSEQ * 64];              // rope (cos,sin)
__device__ __half g_hsh[(size_t)TSEQ * HID], g_hsl[(size_t)TSEQ * HID];
__device__ __half g_wq[(size_t)HID * NH * DH];
__device__ __half g_wk[(size_t)HID * NKV * DH];
__device__ __half g_wv[(size_t)HID * NKV * DH];
__device__ __half g_wo[(size_t)NH * DH * HID];
__device__ __half g_qh[(size_t)TSEQ * NH * DH], g_ql[(size_t)TSEQ * NH * DH];
__device__ __half g_ktr[(size_t)NKV * DH * TSEQ];        // K transposed [h][d][t]
__device__ __half g_v[(size_t)TSEQ * NKV * DH];
__device__ __half g_ah[(size_t)TSEQ * NH * DH], g_al[(size_t)TSEQ * NH * DH];

// ---------------------------------------------------------------------------
// helpers
// ---------------------------------------------------------------------------
__device__ __forceinline__ uint32_t smem_u32(const void* p) {
    uint32_t a;
    asm("{ .reg .u64 t; cvta.to.shared.u64 t, %1; cvt.u32.u64 %0, t; }"
        : "=r"(a) : "l"(p));
    return a;
}
__device__ __forceinline__ uint32_t pack_f16x2(float x, float y) {
    __half2 h = __floats2half2_rn(x, y);
    return *(uint32_t*)&h;
}
__device__ __forceinline__ void split_pack_f16(float x, float y,
                                               uint32_t& hi, uint32_t& lo) {
    __half2 h = __floats2half2_rn(x, y);
    float2 b = __half22float2(h);
    __half2 l = __floats2half2_rn(x - b.x, y - b.y);
    hi = *(uint32_t*)&h;
    lo = *(uint32_t*)&l;
}
__device__ __forceinline__ void ldsm4(uint32_t (&r)[4], uint32_t a) {
    asm volatile("ldmatrix.sync.aligned.m8n8.x4.shared.b16 {%0,%1,%2,%3}, [%4];"
        : "=r"(r[0]), "=r"(r[1]), "=r"(r[2]), "=r"(r[3]) : "r"(a));
}
__device__ __forceinline__ void ldsm4t(uint32_t (&r)[4], uint32_t a) {
    asm volatile("ldmatrix.sync.aligned.m8n8.x4.trans.shared.b16 {%0,%1,%2,%3}, [%4];"
        : "=r"(r[0]), "=r"(r[1]), "=r"(r[2]), "=r"(r[3]) : "r"(a));
}
__device__ __forceinline__ void mma_f16(float (&c)[4], const uint32_t (&a)[4],
                                        uint32_t b0, uint32_t b1) {
    asm volatile("mma.sync.aligned.m16n8k16.row.col.f32.f16.f16.f32 "
        "{%0,%1,%2,%3}, {%4,%5,%6,%7}, {%8,%9}, {%0,%1,%2,%3};"
        : "+f"(c[0]), "+f"(c[1]), "+f"(c[2]), "+f"(c[3])
        : "r"(a[0]), "r"(a[1]), "r"(a[2]), "r"(a[3]), "r"(b0), "r"(b1));
}
__device__ __forceinline__ void cp16(uint32_t dst, const void* src) {
    asm volatile("cp.async.cg.shared.global [%0], [%1], 16;" :: "r"(dst), "l"(src));
}
#define CP_COMMIT() asm volatile("cp.async.commit_group;" ::: "memory")
#define CP_WAIT(n)  asm volatile("cp.async.wait_group %0;" :: "n"(n) : "memory")

// ---------------------------------------------------------------------------
// Fused prep: hs hi/lo split + all 4 weight converts + rope table.
// ---------------------------------------------------------------------------
#define HS_G  (TSEQ * HID / 16)
#define WQ_G  (HID * NH * DH / 16)
#define WK_G  (HID * NKV * DH / 16)
#define WV_G  (HID * NKV * DH / 16)
#define WO_G  (NH * DH * HID / 16)
#define TAB_T (TSEQ * 64)
#define PREP_TOT (HS_G + WQ_G + WK_G + WV_G + WO_G + TAB_T)

__global__ void prep_kernel(const int* __restrict__ positions,
                            const float4* __restrict__ hs,
                            const float4* __restrict__ wq,
                            const float4* __restrict__ wk,
                            const float4* __restrict__ wv,
                            const float4* __restrict__ wo)
{
    int i = blockIdx.x * blockDim.x + threadIdx.x;
    if (i >= PREP_TOT) return;
    int j = i;
    if (j < HS_G) {
        float4 v[4];
        #pragma unroll
        for (int q = 0; q < 4; q++) v[q] = hs[j * 4 + q];
        #pragma unroll
        for (int q = 0; q < 2; q++) {
            uint32_t h0, l0, h1, l1, h2, l2, h3, l3;
            split_pack_f16(v[2*q].x, v[2*q].y, h0, l0);
            split_pack_f16(v[2*q].z, v[2*q].w, h1, l1);
            split_pack_f16(v[2*q+1].x, v[2*q+1].y, h2, l2);
            split_pack_f16(v[2*q+1].z, v[2*q+1].w, h3, l3);
            ((uint4*)g_hsh)[j * 2 + q] = make_uint4(h0, h1, h2, h3);
            ((uint4*)g_hsl)[j * 2 + q] = make_uint4(l0, l1, l2, l3);
        }
        return;
    }
    j -= HS_G;
    const float4* src;
    uint4* dst;
    if (j < WQ_G)                 { src = wq; dst = (uint4*)g_wq; }
    else if ((j -= WQ_G) < WK_G)  { src = wk; dst = (uint4*)g_wk; }
    else if ((j -= WK_G) < WV_G)  { src = wv; dst = (uint4*)g_wv; }
    else if ((j -= WV_G) < WO_G)  { src = wo; dst = (uint4*)g_wo; }
    else {
        j -= WO_G;
        int d = j & 63, t = j >> 6;
        float pos = (float)positions[t];
        float inv_freq = powf(1.0e6f, -(float)d * (1.0f / 64.0f));
        float s, c;
        sincosf(pos * inv_freq, &s, &c);
        g_tab[j] = make_float2(c, s);
        return;
    }
    float4 v[4];
    #pragma unroll
    for (int q = 0; q < 4; q++) v[q] = src[j * 4 + q];
    #pragma unroll
    for (int q = 0; q < 2; q++)
        dst[j * 2 + q] = make_uint4(
            pack_f16x2(v[2*q].x, v[2*q].y),     pack_f16x2(v[2*q].z, v[2*q].w),
            pack_f16x2(v[2*q+1].x, v[2*q+1].y), pack_f16x2(v[2*q+1].z, v[2*q+1].w));
}

// ---------------------------------------------------------------------------
// Core GEMM tile (R13-proven config). Modes as R14.
// ---------------------------------------------------------------------------
#define TG_AT 18432u            // A tile [128][144B]
#define TG_BT 17408u            // B tile [64][272B]
#define TG_BUF (2u * TG_AT + TG_BT)         // 54272
#define TG_SMEM (2u * TG_BUF)               // 108544

__device__ __forceinline__ void gemm_tile(
    const __half* __restrict__ Ah, const __half* __restrict__ Al,
    const __half* __restrict__ B,
    const float* __restrict__ bias, float* __restrict__ C,
    __half* __restrict__ Ch,
    int N, int K, int bm, int bn, char* sm, int mode)
{
    const uint32_t sb = smem_u32(sm);
    const int tid  = threadIdx.x;
    const int wid  = tid >> 5;
    const int lane = tid & 31;
    const int wm = (wid >> 1) << 5;
    const int wn = (wid & 1) << 6;

    auto issue = [&](int k0, int buf) {
        const uint32_t base = sb + (uint32_t)buf * TG_BUF;
        #pragma unroll
        for (int i = 0; i < 4; i++) {
            int idx = tid + i * 256;
            int ar = idx >> 3, ac = idx & 7;
            const size_t aoff = (size_t)(bm + ar) * K + k0 + ac * 8;
            cp16(base + (uint32_t)(ar * 144 + ac * 16), Ah + aoff);
            cp16(base + TG_AT + (uint32_t)(ar * 144 + ac * 16), Al + aoff);
            int br = idx >> 4, bc = idx & 15;
            const size_t boff = (size_t)(k0 + br) * N + bn + bc * 8;
            cp16(base + 2u * TG_AT + (uint32_t)(br * 272 + bc * 16), B + boff);
        }
    };

    float acc[2][8][4];
    #pragma unroll
    for (int mi = 0; mi < 2; mi++)
        #pragma unroll
        for (int j = 0; j < 8; j++)
            #pragma unroll
            for (int q = 0; q < 4; q++) acc[mi][j][q] = 0.f;

    const int NC = K >> 6;
    issue(0, 0); CP_COMMIT();

    for (int c = 0; c < NC; c++) {
        CP_WAIT(0);
        __syncthreads();
        if (c + 1 < NC) { issue((c + 1) << 6, (c + 1) & 1); CP_COMMIT(); }

        const uint32_t base = sb + (uint32_t)(c & 1) * TG_BUF;
        #pragma unroll
        for (int ks = 0; ks < 4; ks++) {
            uint32_t afh[2][4], afl[2][4];
            #pragma unroll
            for (int mi = 0; mi < 2; mi++) {
                uint32_t ro = base + (uint32_t)((wm + mi * 16 + (lane & 15)) * 144
                                                + ks * 32 + (lane >> 4) * 16);
                ldsm4(afh[mi], ro);
                ldsm4(afl[mi], ro + TG_AT);
            }
            uint32_t bf[4][4];
            const uint32_t kro = base + 2u * TG_AT
                + (uint32_t)((ks * 16 + (lane & 15)) * 272 + (lane >> 4) * 16);
            #pragma unroll
            for (int nb = 0; nb < 4; nb++)
                ldsm4t(bf[nb], kro + (uint32_t)((wn + nb * 16) * 2));
            #pragma unroll
            for (int mi = 0; mi < 2; mi++)
                #pragma unroll
                for (int nb = 0; nb < 4; nb++)
                    #pragma unroll
                    for (int hh = 0; hh < 2; hh++) {
                        float (&cc)[4] = acc[mi][nb * 2 + hh];
                        mma_f16(cc, afh[mi], bf[nb][2 * hh], bf[nb][2 * hh + 1]);
                        mma_f16(cc, afl[mi], bf[nb][2 * hh], bf[nb][2 * hh + 1]);
                    }
        }
    }

    const int r0 = lane >> 2;
    const int c0 = (lane & 3) << 1;

    if (mode <= 1) {
        #pragma unroll
        for (int mi = 0; mi < 2; mi++) {
            #pragma unroll
            for (int j = 0; j < 8; j++) {
                const int col = bn + wn + j * 8 + c0;
                float bias0 = 0.f, bias1 = 0.f;
                if (bias != nullptr) { bias0 = bias[col]; bias1 = bias[col + 1]; }
                const int row_a = bm + wm + mi * 16 + r0;
                const int row_b = row_a + 8;
                float va0 = acc[mi][j][0] + bias0, va1 = acc[mi][j][1] + bias1;
                float vb0 = acc[mi][j][2] + bias0, vb1 = acc[mi][j][3] + bias1;
                float* Ca = C + (size_t)row_a * N + col;
                float* Cb = C + (size_t)row_b * N + col;
                Ca[0] = va0; Ca[1] = va1;
                Cb[0] = vb0; Cb[1] = vb1;
                if (mode == 1) {
                    *(uint32_t*)(Ch + (size_t)row_a * N + col) = pack_f16x2(va0, va1);
                    *(uint32_t*)(Ch + (size_t)row_b * N + col) = pack_f16x2(vb0, vb1);
                }
            }
        }
        return;
    }

    // ---- rope modes: stage fp32 tile (+bias) to smem [128][132] ----
    float* S = (float*)sm;
    __syncthreads();
    #pragma unroll
    for (int mi = 0; mi < 2; mi++) {
        #pragma unroll
        for (int j = 0; j < 8; j++) {
            const int scol = wn + j * 8 + c0;
            float bias0 = 0.f, bias1 = 0.f;
            if (bias != nullptr) { bias0 = bias[bn + scol]; bias1 = bias[bn + scol + 1]; }
            const int sra = wm + mi * 16 + r0;
            S[sra * 132 + scol]           = acc[mi][j][0] + bias0;
            S[sra * 132 + scol + 1]       = acc[mi][j][1] + bias1;
            S[(sra + 8) * 132 + scol]     = acc[mi][j][2] + bias0;
            S[(sra + 8) * 132 + scol + 1] = acc[mi][j][3] + bias1;
        }
    }
    __syncthreads();

    const int head = bn >> 7;
    if (mode == 2) {
        const float scale = 0.08838834764831843f;
        for (int i = tid; i < 128 * 32; i += 256) {
            int dp = i & 31, r = i >> 5;
            int d = dp * 2;
            int t = bm + r;
            float2 cs0 = g_tab[t * 64 + d];
            float2 cs1 = g_tab[t * 64 + d + 1];
            float x1a = S[r * 132 + d],      x1b = S[r * 132 + d + 1];
            float x2a = S[r * 132 + d + 64], x2b = S[r * 132 + d + 65];
            float y1a = (x1a * cs0.x - x2a * cs0.y) * scale;
            float y2a = (x2a * cs0.x + x1a * cs0.y) * scale;
            float y1b = (x1b * cs1.x - x2b * cs1.y) * scale;
            float y2b = (x2b * cs1.x + x1b * cs1.y) * scale;
            uint32_t h1_, l1_, h2_, l2_;
            split_pack_f16(y1a, y1b, h1_, l1_);
            split_pack_f16(y2a, y2b, h2_, l2_);
            const size_t go = (size_t)t * (NH * DH) + (size_t)head * DH + d;
            *(uint32_t*)(g_qh + go)      = h1_;
            *(uint32_t*)(g_ql + go)      = l1_;
            *(uint32_t*)(g_qh + go + 64) = h2_;
            *(uint32_t*)(g_ql + go + 64) = l2_;
        }
    } else {
        for (int i = tid; i < 128 * 32; i += 256) {
            int dp = i & 31, r = i >> 5;
            int d = dp * 2;
            int t = bm + r;
            float2 cs0 = g_tab[t * 64 + d];
            float2 cs1 = g_tab[t * 64 + d + 1];
            float x1a = S[r * 132 + d],      x1b = S[r * 132 + d + 1];
            float x2a = S[r * 132 + d + 64], x2b = S[r * 132 + d + 65];
            float y1a = x1a * cs0.x - x2a * cs0.y;
            float y2a = x2a * cs0.x + x1a * cs0.y;
            float y1b = x1b * cs1.x - x2b * cs1.y;
            float y2b = x2b * cs1.x + x1b * cs1.y;
            float* Cp = C + (size_t)t * (NKV * DH) + (size_t)head * DH + d;
            *(float2*)Cp        = make_float2(y1a, y1b);
            *(float2*)(Cp + 64) = make_float2(y2a, y2b);
        }
        for (int i = tid; i < 64 * 128; i += 256) {
            int r = i & 127, d = i >> 7;
            int t = bm + r;
            float2 cs = g_tab[t * 64 + d];
            float x1 = S[r * 132 + d];
            float x2 = S[r * 132 + d + 64];
            float y1 = x1 * cs.x - x2 * cs.y;
            float y2 = x2 * cs.x + x1 * cs.y;
            g_ktr[((size_t)head * DH + d) * TSEQ + t]      = __float2half_rn(y1);
            g_ktr[((size_t)head * DH + d + 64) * TSEQ + t] = __float2half_rn(y2);
        }
    }
}

// Fused QKV projection + rope: grid (16, 48), heavy CTAs first:
// by<8 -> K (rope->fp32 + ktr), [8,40) -> Q (rope->split fp16), [40,48) -> V.
__global__ __launch_bounds__(256, 2) void tgemm_qkv(
    const float* __restrict__ bq, const float* __restrict__ bk,
    const float* __restrict__ bv,
    float* __restrict__ kout, float* __restrict__ vout)
{
    extern __shared__ char sm[];
    const int by = blockIdx.y;
    const int bm = (int)blockIdx.x << 7;
    if (by < 8) {
        gemm_tile(g_hsh, g_hsl, g_wk, bk, kout, nullptr,
                  NKV * DH, HID, bm, by << 7, sm, 3);
    } else if (by < 40) {
        gemm_tile(g_hsh, g_hsl, g_wq, bq, nullptr, nullptr,
                  NH * DH, HID, bm, (by - 8) << 7, sm, 2);
    } else {
        gemm_tile(g_hsh, g_hsl, g_wv, bv, vout, g_v,
                  NKV * DH, HID, bm, (by - 40) << 7, sm, 1);
    }
}

// O projection: grid (16, 32).
__global__ __launch_bounds__(256, 2) void tgemm_o(float* __restrict__ out)
{
    extern __shared__ char sm[];
    gemm_tile(g_ah, g_al, g_wo, nullptr, out, nullptr,
              HID, NH * DH, (int)blockIdx.x << 7, (int)blockIdx.y << 7, sm, 0);
}

// ---------------------------------------------------------------------------
// MMA flash attention: 64 q-rows/CTA, 128 threads (4 warps x 16 rows).
// smem 106.5KB -> 2 CTAs/SM. Q fp16 hi/lo (pre-scaled), K/V plain fp16
// (K pre-transposed), P split x2, cp.async 2-stage KV. Grid (NH, 32), m0 rev.
// ---------------------------------------------------------------------------
#define A3_Q  17408u    // [64][272B]
#define A3_KT 18432u    // [128][144B]
#define A3_V  17408u    // [64][272B]
#define P_QH 0u
#define P_QL A3_Q
#define P_KV0 (2u * A3_Q)
#define KV3_BUF (A3_KT + A3_V)
#define A3_SMEM (2u * A3_Q + 2u * KV3_BUF)   // 106496

__global__ __launch_bounds__(128, 2) void attn_mma(
    __half* __restrict__ oh, __half* __restrict__ ol)
{
    extern __shared__ char sm[];
    const uint32_t sb = smem_u32(sm);
    const int h  = blockIdx.x;
    const int m0 = (int)(gridDim.y - 1 - blockIdx.y) << 6;
    const int kvh = h / GRP;
    const int tid = threadIdx.x;
    const int wid = tid >> 5;
    const int lane = tid & 31;
    const int wm = wid << 4;          // 16 q-rows per warp
    const int gID = lane >> 2;
    const int tig = lane & 3;

    const __half* ktr_h = g_ktr + (size_t)kvh * DH * TSEQ;

    auto issue_kv = [&](int n0, int b) {
        const uint32_t kb = sb + P_KV0 + (uint32_t)b * KV3_BUF;
        #pragma unroll
        for (int i = 0; i < 8; i++) {
            int idx = tid + i * 128;
            int dr = idx >> 3, dc = idx & 7;
            cp16(kb + (uint32_t)(dr * 144 + dc * 16),
                 ktr_h + (size_t)dr * TSEQ + n0 + dc * 8);
            int vr = idx >> 4, vc = idx & 15;
            cp16(kb + A3_KT + (uint32_t)(vr * 272 + vc * 16),
                 g_v + (size_t)(n0 + vr) * (NKV * DH) + (size_t)kvh * DH + vc * 8);
        }
    };

    // load Q tile (64 x 128) hi/lo
    #pragma unroll
    for (int i = 0; i < 8; i++) {
        int idx = tid + i * 128;
        int r = idx >> 4, ch = idx & 15;
        const size_t go = (size_t)(m0 + r) * (NH * DH) + (size_t)h * DH + ch * 8;
        *(uint4*)(sm + P_QH + r * 272 + ch * 16) = *(const uint4*)(g_qh + go);
        *(uint4*)(sm + P_QL + r * 272 + ch * 16) = *(const uint4*)(g_ql + go);
    }

    float oacc[16][4];
    #pragma unroll
    for (int j = 0; j < 16; j++)
        #pragma unroll
        for (int q = 0; q < 4; q++) oacc[j][q] = 0.f;
    float m_run0 = -1e30f, m_run1 = -1e30f, l_run0 = 0.f, l_run1 = 0.f;

    const int row0 = m0 + wm + gID;
    const int row1 = row0 + 8;
    const int warp_max_row = m0 + wm + 15;

    const int nblocks = (m0 >> 6) + 1;
    issue_kv(0, 0); CP_COMMIT();

    for (int blk = 0; blk < nblocks; blk++) {
        const int n0 = blk << 6;
        const bool more = (blk + 1 < nblocks);
        if (more) { issue_kv((blk + 1) << 6, (blk + 1) & 1); CP_COMMIT(); CP_WAIT(1); }
        else      { CP_WAIT(0); }
        __syncthreads();

        if (n0 <= warp_max_row) {
            const uint32_t kb = sb + P_KV0 + (uint32_t)(blk & 1) * KV3_BUF;

            // ---- S = Q K^T (2 products) ----
            float sacc[8][4];
            #pragma unroll
            for (int j = 0; j < 8; j++)
                #pragma unroll
                for (int q = 0; q < 4; q++) sacc[j][q] = 0.f;

            #pragma unroll
            for (int ks = 0; ks < 8; ks++) {
                uint32_t aH[4], aL[4];
                uint32_t ro = sb + P_QH + (uint32_t)((wm + (lane & 15)) * 272
                                                     + ks * 32 + (lane >> 4) * 16);
                ldsm4(aH, ro);
                ldsm4(aL, ro + A3_Q);
                const uint32_t kro = kb
                    + (uint32_t)((ks * 16 + (lane & 15)) * 144 + (lane >> 4) * 16);
                #pragma unroll
                for (int nb = 0; nb < 4; nb++) {
                    uint32_t bk4[4];
                    ldsm4t(bk4, kro + (uint32_t)(nb * 32));
                    #pragma unroll
                    for (int hh = 0; hh < 2; hh++) {
                        float (&cc)[4] = sacc[nb * 2 + hh];
                        mma_f16(cc, aH, bk4[2 * hh], bk4[2 * hh + 1]);
                        mma_f16(cc, aL, bk4[2 * hh], bk4[2 * hh + 1]);
                    }
                }
            }

            // ---- online softmax ----
            float mx0 = -1e30f, mx1 = -1e30f;
            #pragma unroll
            for (int nb = 0; nb < 8; nb++) {
                #pragma unroll
                for (int j = 0; j < 2; j++) {
                    const int col = n0 + nb * 8 + tig * 2 + j;
                    float s0 = sacc[nb][j];
                    float s1 = sacc[nb][2 + j];
                    if (col > row0) s0 = -1e30f;
                    if (col > row1) s1 = -1e30f;
                    sacc[nb][j] = s0;
                    sacc[nb][2 + j] = s1;
                    mx0 = fmaxf(mx0, s0);
                    mx1 = fmaxf(mx1, s1);
                }
            }
            #pragma unroll
            for (int off = 1; off <= 2; off <<= 1) {
                mx0 = fmaxf(mx0, __shfl_xor_sync(0xffffffffu, mx0, off));
                mx1 = fmaxf(mx1, __shfl_xor_sync(0xffffffffu, mx1, off));
            }
            float mn0 = fmaxf(m_run0, mx0);
            float mn1 = fmaxf(m_run1, mx1);
            float cf0 = __expf(m_run0 - mn0);
            float cf1 = __expf(m_run1 - mn1);
            m_run0 = mn0; m_run1 = mn1;
            float su0 = 0.f, su1 = 0.f;
            #pragma unroll
            for (int nb = 0; nb < 8; nb++) {
                #pragma unroll
                for (int j = 0; j < 2; j++) {
                    float p0 = __expf(sacc[nb][j] - mn0);
                    float p1 = __expf(sacc[nb][2 + j] - mn1);
                    sacc[nb][j] = p0;
                    sacc[nb][2 + j] = p1;
                    su0 += p0;
                    su1 += p1;
                }
            }
            #pragma unroll
            for (int off = 1; off <= 2; off <<= 1) {
                su0 += __shfl_xor_sync(0xffffffffu, su0, off);
                su1 += __shfl_xor_sync(0xffffffffu, su1, off);
            }
            l_run0 = l_run0 * cf0 + su0;
            l_run1 = l_run1 * cf1 + su1;
            #pragma unroll
            for (int j = 0; j < 16; j++) {
                oacc[j][0] *= cf0;
                oacc[j][1] *= cf0;
                oacc[j][2] *= cf1;
                oacc[j][3] *= cf1;
            }

            // ---- O += P V (2 products; P split register-direct) ----
            #pragma unroll
            for (int ks = 0; ks < 4; ks++) {
                uint32_t ph[4], pl[4];
                split_pack_f16(sacc[2 * ks][0],     sacc[2 * ks][1],     ph[0], pl[0]);
                split_pack_f16(sacc[2 * ks][2],     sacc[2 * ks][3],     ph[1], pl[1]);
                split_pack_f16(sacc[2 * ks + 1][0], sacc[2 * ks + 1][1], ph[2], pl[2]);
                split_pack_f16(sacc[2 * ks + 1][2], sacc[2 * ks + 1][3], ph[3], pl[3]);
                const uint32_t vro = kb + A3_KT
                    + (uint32_t)((ks * 16 + (lane & 15)) * 272 + (lane >> 4) * 16);
                #pragma unroll
                for (int nbv = 0; nbv < 8; nbv++) {
                    uint32_t vb4[4];
                    ldsm4t(vb4, vro + (uint32_t)(nbv * 32));
                    #pragma unroll
                    for (int hh = 0; hh < 2; hh++) {
                        float (&cc)[4] = oacc[nbv * 2 + hh];
                        mma_f16(cc, ph, vb4[2 * hh], vb4[2 * hh + 1]);
                        mma_f16(cc, pl, vb4[2 * hh], vb4[2 * hh + 1]);
                    }
                }
            }
        }
        __syncthreads();
    }

    // epilogue: write fp16 hi/lo split of normalized output
    const float inv0 = 1.0f / l_run0;
    const float inv1 = 1.0f / l_run1;
    #pragma unroll
    for (int onb = 0; onb < 16; onb++) {
        const int col = h * DH + onb * 8 + tig * 2;
        const size_t i0 = (size_t)row0 * (NH * DH) + col;
        const size_t i1 = (size_t)row1 * (NH * DH) + col;
        uint32_t hh_, ll_;
        split_pack_f16(oacc[onb][0] * inv0, oacc[onb][1] * inv0, hh_, ll_);
        *(uint32_t*)(oh + i0) = hh_;
        *(uint32_t*)(ol + i0) = ll_;
        split_pack_f16(oacc[onb][2] * inv1, oacc[onb][3] * inv1, hh_, ll_);
        *(uint32_t*)(oh + i1) = hh_;
        *(uint32_t*)(ol + i1) = ll_;
    }
}

// ---------------------------------------------------------------------------
extern "C" void kernel_launch(void* const* d_in, const int* in_sizes, int n_in,
                              void* d_out, int out_size)
{
    const int*   positions = (const int*)d_in[0];
    const float* hs = (const float*)d_in[1];
    const float* Wq = (const float*)d_in[2];
    const float* bq = (const float*)d_in[3];
    const float* Wk = (const float*)d_in[4];
    const float* bk = (const float*)d_in[5];
    const float* Wv = (const float*)d_in[6];
    const float* bv = (const float*)d_in[7];
    const float* Wo = (const float*)d_in[8];

    float* out  = (float*)d_out;
    float* kout = out + (size_t)TSEQ * HID;
    float* vout = kout + (size_t)TSEQ * NKV * DH;

    __half *aah, *aal;
    cudaGetSymbolAddress((void**)&aah, g_ah);
    cudaGetSymbolAddress((void**)&aal, g_al);

    cudaFuncSetAttribute(tgemm_qkv, cudaFuncAttributeMaxDynamicSharedMemorySize, (int)TG_SMEM);
    cudaFuncSetAttribute(tgemm_o, cudaFuncAttributeMaxDynamicSharedMemorySize, (int)TG_SMEM);
    cudaFuncSetAttribute(attn_mma, cudaFuncAttributeMaxDynamicSharedMemorySize, (int)A3_SMEM);

    // 1. fused prep (hs split, weight converts, rope table)
    prep_kernel<<<(PREP_TOT + 255) / 256, 256>>>(
        positions, (const float4*)hs, (const float4*)Wq, (const float4*)Wk,
        (const float4*)Wv, (const float4*)Wo);

    // 2. fused QKV projection + rope
    tgemm_qkv<<<dim3(16, 48), 256, TG_SMEM>>>(bq, bk, bv, kout, vout);

    // 3. attention (64 q-rows/CTA, 2 CTAs/SM)
    attn_mma<<<dim3(NH, TSEQ / 64), 128, A3_SMEM>>>(aah, aal);

    // 4. O projection
    tgemm_o<<<dim3(16, 32), 256, TG_SMEM>>>(out);
}